// round 3
// baseline (speedup 1.0000x reference)
#include <cuda_runtime.h>
#include <cstddef>

// FlowNet-C correlation on GB300.
// x1,x2: [4,128,96,96] f32.  out: [4, 41*41, 48, 48] f32.
// out[b, i*41+j, oh, ow] = 1/(128*4) * sum_{c, p,q in {0,1}}
//      x1[b,c,2oh+p,2ow+q] * x2pad[b,c,2oh+p+j, 2ow+q+i]   (pad=20 zeros)

#define BATCH 4
#define CHAN  128
#define HH    96
#define WW    96
#define MD    20
#define KD    41
#define OHH   48
#define OWW   48

#define TILE  8       // pooled tile 8x8
#define JG    7       // j per CTA (6 groups cover 0..41, j=41 discarded)
#define IGL   21      // i per ig group; warp covers one ig, CTA covers both
#define CC    4       // channels per pipeline chunk
#define NCHUNK (CHAN / CC)   // 32

#define NTHREADS 448  // 14 warps = 7 (j) x 2 (ig); lane = 4 owsl x 8 ohl

// x2 smem: per channel, 21 overlapping row-pairs of 57 f32x2 cols.
// Row stride 59 (odd) + (s>>2)&1 element swizzle -> conflict-free LDS.64.
#define X2_SSTRIDE 59
#define X2_PLANE   (21 * X2_SSTRIDE + 2)   // 1241 u64
#define X1_PLANE   (8 * 17)                // 136 u64
#define BUFSZ      (CC * (X2_PLANE + X1_PLANE))   // 5508 u64 per buffer

typedef unsigned long long u64;

__device__ __forceinline__ u64 pack2(float a, float b) {
    u64 r; asm("mov.b64 %0, {%1, %2};" : "=l"(r) : "f"(a), "f"(b)); return r;
}
__device__ __forceinline__ void fma2(u64& d, u64 a, u64 b) {
    asm("fma.rn.f32x2 %0, %1, %2, %0;" : "+l"(d) : "l"(a), "l"(b));
}
__device__ __forceinline__ void unpack2(u64 v, float& x, float& y) {
    asm("mov.b64 {%0, %1}, %2;" : "=f"(x), "=f"(y) : "l"(v));
}

__global__ void __launch_bounds__(NTHREADS, 1)
corr_kernel(const float* __restrict__ x1g, const float* __restrict__ x2g,
            float* __restrict__ outg)
{
    extern __shared__ u64 sm[];

    const int tid  = threadIdx.x;
    const int lane = tid & 31;
    const int warp = tid >> 5;
    const int tj   = warp % 7;            // j offset within group
    const int ig   = warp / 7;            // 0..1 : i group
    const int owsl = lane & 3;            // pixel-pair slot along ow
    const int ohl  = lane >> 2;           // pooled row within tile

    const int tx = blockIdx.x % (OWW / TILE);
    const int ty = blockIdx.x / (OWW / TILE);
    const int j0 = blockIdx.y * JG;
    const int b  = blockIdx.z;

    const int oh0 = ty * TILE, ow0 = tx * TILE;
    const int base_r = 2 * oh0 + j0;      // x2pad row of pair s=0
    const int col0   = 2 * ow0;           // x2pad col of local col 0

    // ---- divide-free fill precompute: 3 x2 slots / thread / channel ----
    int  off2[3], go2[3];
    bool okA[3], okB[3], okS[3];
#pragma unroll
    for (int k = 0; k < 3; ++k) {
        int t    = tid + k * NTHREADS;    // < 1344 = 21*64
        int ss   = t >> 6;                // row-pair 0..20
        int colL = t & 63;                // padded col; valid < 57
        int gr = base_r + ss - MD;
        int gc = col0 + colL - MD;
        bool okc = (colL < 57) && ((unsigned)gc < WW);
        okA[k] = okc && ((unsigned)gr < HH);
        okB[k] = okc && ((unsigned)(gr + 1) < HH);
        okS[k] = (colL < 57);
        go2[k] = gr * WW + gc;
        off2[k] = ss * X2_SSTRIDE + ((ss >> 2) & 1) + colL;
    }
    // x1 slots: CC*128 = 512 elems; thread handles tid, plus tid+448 if tid<64
    const int n1 = (tid < 64) ? 2 : 1;
    int go1[2], so1[2];
#pragma unroll
    for (int m = 0; m < 2; ++m) {
        int e = tid + m * NTHREADS;       // < 512
        int c = e >> 7, r = e & 127, rp = r >> 4, cl = r & 15;
        go1[m] = c * (HH * WW) + (2 * oh0 + 2 * rp) * WW + col0 + cl;
        so1[m] = c * X1_PLANE + rp * 17 + cl;
    }

    const size_t gbase1 = (size_t)b * CHAN * (HH * WW);

    // fill registers (single staged set: holds chunk ch+1 during COMPUTE(ch))
    float rA[CC][3], rB[CC][3], rU[2], rV[2];

#define LOADCH(CH)                                                           \
    {                                                                        \
        _Pragma("unroll")                                                    \
        for (int c = 0; c < CC; ++c) {                                       \
            const float* p = x2g + gbase1 + ((size_t)((CH) * CC + c)) * (HH * WW); \
            _Pragma("unroll")                                                \
            for (int k = 0; k < 3; ++k) {                                    \
                rA[c][k] = okA[k] ? p[go2[k]] : 0.f;                         \
                rB[c][k] = okB[k] ? p[go2[k] + WW] : 0.f;                    \
            }                                                                \
        }                                                                    \
        const float* q = x1g + gbase1 + (size_t)(CH) * CC * (HH * WW);       \
        _Pragma("unroll")                                                    \
        for (int m = 0; m < 2; ++m)                                          \
            if (m < n1) { rU[m] = q[go1[m]]; rV[m] = q[go1[m] + WW]; }       \
    }

#define STSCH(BUF)                                                           \
    {                                                                        \
        u64* x2s = sm + (BUF) * BUFSZ;                                       \
        u64* x1s = x2s + CC * X2_PLANE;                                      \
        _Pragma("unroll")                                                    \
        for (int c = 0; c < CC; ++c) {                                       \
            _Pragma("unroll")                                                \
            for (int k = 0; k < 3; ++k)                                      \
                if (okS[k]) x2s[c * X2_PLANE + off2[k]] = pack2(rA[c][k], rB[c][k]); \
        }                                                                    \
        _Pragma("unroll")                                                    \
        for (int m = 0; m < 2; ++m)                                          \
            if (m < n1) x1s[so1[m]] = pack2(rU[m], rV[m]);                   \
    }

    // ---- accumulators ----
    u64 acc0[IGL], acc1[IGL];
#pragma unroll
    for (int il = 0; il < IGL; ++il) { acc0[il] = 0ull; acc1[il] = 0ull; }

    const int s = 2 * ohl + tj;                    // this thread's row-pair
    const int rbase = s * X2_SSTRIDE + ((s >> 2) & 1) + 4 * owsl + IGL * ig;
    const int abase = ohl * 17 + 4 * owsl;

    // ---- pipeline prolog ----
    LOADCH(0);
    STSCH(0);
    LOADCH(1);
    __syncthreads();

    for (int ch = 0; ch < NCHUNK; ++ch) {
        if (ch + 1 < NCHUNK) {
            STSCH((ch + 1) & 1);          // store staged chunk ch+1
            if (ch + 2 < NCHUNK) LOADCH(ch + 2);   // refill stage regs
        }
        // ---- compute chunk ch ----
        {
            const u64* x2s = sm + (ch & 1) * BUFSZ;
            const u64* x1s = x2s + CC * X2_PLANE;
#pragma unroll
            for (int c = 0; c < CC; ++c) {
                const u64* row = x2s + c * X2_PLANE + rbase;
                const u64* xr  = x1s + c * X1_PLANE + abase;
                u64 a0 = xr[0], a1 = xr[1], a2 = xr[2], a3 = xr[3];
                u64 w0 = row[0], w1 = row[1], w2 = row[2];
#pragma unroll
                for (int il = 0; il < IGL; ++il) {
                    u64 w3 = row[il + 3];
                    fma2(acc0[il], a0, w0);
                    fma2(acc0[il], a1, w1);
                    fma2(acc1[il], a2, w2);
                    fma2(acc1[il], a3, w3);
                    w0 = w1; w1 = w2; w2 = w3;
                }
            }
        }
        __syncthreads();
    }

    // ---- epilogue ----
    const int j = j0 + tj;
    if (j < KD) {
        const int oh = oh0 + ohl;
        const int owA = ow0 + 2 * owsl;
        const float scale = 1.0f / (CHAN * 4);
#pragma unroll
        for (int il = 0; il < IGL; ++il) {
            int i = IGL * ig + il;
            if (i < KD) {
                int chn = i * KD + j;
                float ax, ay, bx, by;
                unpack2(acc0[il], ax, ay);
                unpack2(acc1[il], bx, by);
                size_t base = (((size_t)b * (KD * KD) + chn) * OHH + oh) * OWW + owA;
                outg[base]     = (ax + ay) * scale;
                outg[base + 1] = (bx + by) * scale;
            }
        }
    }
}

extern "C" void kernel_launch(void* const* d_in, const int* in_sizes, int n_in,
                              void* d_out, int out_size)
{
    (void)in_sizes; (void)n_in; (void)out_size;
    const float* x1 = (const float*)d_in[0];
    const float* x2 = (const float*)d_in[1];
    float* out = (float*)d_out;

    const int smem = 2 * BUFSZ * (int)sizeof(u64);  // 88128 B
    static bool attr_set = false;
    if (!attr_set) {
        cudaFuncSetAttribute(corr_kernel, cudaFuncAttributeMaxDynamicSharedMemorySize, smem);
        attr_set = true;
    }

    dim3 grid(36, 6, BATCH);   // 36 tiles x 6 j-groups x batch
    dim3 block(NTHREADS);
    corr_kernel<<<grid, block, smem>>>(x1, x2, out);
}

// round 5
// speedup vs baseline: 3.6567x; 3.6567x over previous
#include <cuda_runtime.h>
#include <cuda_fp16.h>
#include <cstdint>
#include <cstddef>

#define BATCH 4
#define CHAN  128
#define HH    96
#define WW    96
#define MD    20
#define KD    41
#define OHH   48
#define OWW   48

// fp16 channel-last staging: x[b][h][w][ch]
__device__ __half x1t_g[BATCH * HH * WW * CHAN];
__device__ __half x2t_g[BATCH * HH * WW * CHAN];

// ---------- prepass: fp32 [b][ch][h][w] -> fp16 [b][h][w][ch] ----------
#define CVT_S 97
__global__ void __launch_bounds__(256, 1)
cvt_kernel(const float* __restrict__ x1, const float* __restrict__ x2)
{
    extern __shared__ float tsm[];                 // [CHAN][CVT_S]
    const int h = blockIdx.x, b = blockIdx.y;
    const float* src = (blockIdx.z == 0) ? x1 : x2;
    __half* dst = (blockIdx.z == 0) ? x1t_g : x2t_g;
    const float* sp = src + ((size_t)b * CHAN) * (HH * WW) + (size_t)h * WW;
    for (int idx = threadIdx.x; idx < CHAN * WW; idx += 256) {
        int ch = idx / WW, w = idx - ch * WW;
        tsm[ch * CVT_S + w] = sp[(size_t)ch * (HH * WW) + w];
    }
    __syncthreads();
    __half* dp = dst + ((size_t)(b * HH + h)) * WW * CHAN;
    for (int idx = threadIdx.x; idx < WW * (CHAN / 2); idx += 256) {
        int w = idx >> 6, cp = idx & 63;
        __half2 hv = __floats2half2_rn(tsm[(2 * cp) * CVT_S + w],
                                       tsm[(2 * cp + 1) * CVT_S + w]);
        *reinterpret_cast<__half2*>(dp + (size_t)w * CHAN + 2 * cp) = hv;
    }
}

// ---------- main kernel ----------
#define NT     384
#define SLAB   24576                     // 96 rows x 256B
#define SA0    0
#define SA1    SLAB
#define SB     (2 * SLAB)                // 3-slot ring
#define SCB    (5 * SLAB)                // 122880
#define CBST   66                        // Cbuf row stride (floats)
#define CBPL   (16 * CBST * 4)           // 4224 B per row-block plane
#define SMEM_MAIN (SCB + 6 * CBPL)       // 148224 B

__device__ __forceinline__ uint32_t smem_u32(const void* p) {
    uint32_t a;
    asm("{ .reg .u64 t; cvta.to.shared.u64 t, %1; cvt.u32.u64 %0, t; }" : "=r"(a) : "l"(p));
    return a;
}

// cp.async 16B, zero-fill when sz==0
__device__ __forceinline__ void cpa16(uint32_t dst, const void* src, uint32_t sz) {
    asm volatile("cp.async.ca.shared.global [%0], [%1], 16, %2;"
                 :: "r"(dst), "l"(src), "r"(sz) : "memory");
}

// fill one 96x128-half slab: row n chunk c -> smem n*256 + ((c^(n&7))<<4)
__device__ __forceinline__ void fill_slab(uint32_t dstb, const __half* src,
                                          bool valid, int tid)
{
#pragma unroll
    for (int it = 0; it < 4; ++it) {
        int q = tid + it * NT;            // < 1536
        int n = q >> 4, c = q & 15;
        uint32_t dst = dstb + n * 256 + ((c ^ (n & 7)) << 4);
        cpa16(dst, src + n * CHAN + c * 8, valid ? 16u : 0u);
    }
}

__device__ __forceinline__ void ldsm4(uint32_t& r0, uint32_t& r1, uint32_t& r2,
                                      uint32_t& r3, uint32_t a) {
    asm volatile("ldmatrix.sync.aligned.m8n8.x4.shared.b16 {%0,%1,%2,%3}, [%4];"
                 : "=r"(r0), "=r"(r1), "=r"(r2), "=r"(r3) : "r"(a));
}
__device__ __forceinline__ void mma16816(float* c, uint32_t a0, uint32_t a1,
                                         uint32_t a2, uint32_t a3,
                                         uint32_t b0, uint32_t b1) {
    asm volatile("mma.sync.aligned.m16n8k16.row.col.f32.f16.f16.f32 "
                 "{%0,%1,%2,%3},{%4,%5,%6,%7},{%8,%9},{%0,%1,%2,%3};"
                 : "+f"(c[0]), "+f"(c[1]), "+f"(c[2]), "+f"(c[3])
                 : "r"(a0), "r"(a1), "r"(a2), "r"(a3), "r"(b0), "r"(b1));
}

__global__ void __launch_bounds__(NT, 1)
corr_hmma_kernel(float* __restrict__ outg)
{
    extern __shared__ char smc[];
    const uint32_t sb = smem_u32(smc);
    const int tid = threadIdx.x, warp = tid >> 5, lane = tid & 31;
    const int m = warp >> 1;              // row block 0..5
    const int nh = warp & 1;              // n-half 0..1
    const int jb = blockIdx.x, oh = blockIdx.y, b = blockIdx.z;
    const int j0 = jb * 21;
    const int cnt = jb ? 20 : 21;
    const int R0 = 2 * oh + j0 - MD;

    // ---- prolog fills (group 0): A slabs + B rows R0, R0+1 ----
    const __half* x1b = x1t_g + ((size_t)(b * HH + 2 * oh)) * WW * CHAN;
    fill_slab(sb + SA0, x1b, true, tid);
    fill_slab(sb + SA1, x1b + WW * CHAN, true, tid);
    const __half* x2bb = x2t_g + (size_t)b * HH * WW * CHAN;
#pragma unroll
    for (int k = 0; k < 2; ++k) {
        int row = R0 + k;
        bool v = (unsigned)row < HH;
        fill_slab(sb + SB + k * SLAB, x2bb + (size_t)(v ? row : 0) * WW * CHAN, v, tid);
    }
    asm volatile("cp.async.commit_group;" ::: "memory");

    // ---- per-thread ldmatrix addressing precompute ----
    const int cs = min(max(16 * m - 24, 0), 32);          // band window start
    const int ra = m * 16 + (lane & 15);
    const uint32_t aoff = (uint32_t)(ra * 256);
    const int swa = ra & 7;
    const int ahi = lane >> 4;                             // A k-hi bit
    int rb0 = cs + (nh * 4 + 0 + (lane >> 4)) * 8 + (lane & 7);
    int rb1 = cs + (nh * 4 + 2 + (lane >> 4)) * 8 + (lane & 7);
    const uint32_t boff0 = (uint32_t)(rb0 * 256);
    const uint32_t boff1 = (uint32_t)(rb1 * 256);
    const int swb0 = rb0 & 7, swb1 = rb1 & 7;
    const int bhi = (lane >> 3) & 1;                       // B k-hi bit

    float* Cbm = reinterpret_cast<float*>(smc + SCB + m * CBPL);
    const int gr = lane >> 2, ccl = 2 * (lane & 3);

    for (int l = 0; l < cnt; ++l) {
        // prefetch B row R0+l+2 into slot (l+2)%3
        if (l + 2 <= cnt) {
            int row = R0 + l + 2;
            bool v = (unsigned)row < HH;
            fill_slab(sb + SB + ((l + 2) % 3) * SLAB,
                      x2bb + (size_t)(v ? row : 0) * WW * CHAN, v, tid);
        }
        asm volatile("cp.async.commit_group;" ::: "memory");
        asm volatile("cp.async.wait_group 1;" ::: "memory");
        __syncthreads();

        // ---- banded GEMM j = j0+l: acc over K = 2 halves x 8 k16-steps ----
        float acc[4][4];
#pragma unroll
        for (int t = 0; t < 4; ++t)
#pragma unroll
            for (int q = 0; q < 4; ++q) acc[t][q] = 0.f;

#pragma unroll
        for (int h = 0; h < 2; ++h) {
            const uint32_t ab = sb + (h ? SA1 : SA0) + aoff;
            const uint32_t bb = sb + SB + (uint32_t)(((l + h) % 3) * SLAB);
#pragma unroll
            for (int ks = 0; ks < 8; ++ks) {
                uint32_t a0, a1, a2, a3, b0, b1, b2, b3;
                ldsm4(a0, a1, a2, a3, ab + (((2 * ks + ahi) ^ swa) << 4));
                ldsm4(b0, b1, b2, b3, bb + boff0 + (((2 * ks + bhi) ^ swb0) << 4));
                mma16816(acc[0], a0, a1, a2, a3, b0, b1);
                mma16816(acc[1], a0, a1, a2, a3, b2, b3);
                ldsm4(b0, b1, b2, b3, bb + boff1 + (((2 * ks + bhi) ^ swb1) << 4));
                mma16816(acc[2], a0, a1, a2, a3, b0, b1);
                mma16816(acc[3], a0, a1, a2, a3, b2, b3);
            }
        }

        // ---- spill band patch to Cbuf ----
#pragma unroll
        for (int t = 0; t < 4; ++t) {
            int n = nh * 4 + t;
            float2 v0 = make_float2(acc[t][0], acc[t][1]);
            float2 v1 = make_float2(acc[t][2], acc[t][3]);
            *reinterpret_cast<float2*>(Cbm + gr * CBST + n * 8 + ccl) = v0;
            *reinterpret_cast<float2*>(Cbm + (gr + 8) * CBST + n * 8 + ccl) = v1;
        }
        __syncthreads();

        // ---- banded gather -> out ----
        const int jglob = j0 + l;
        for (int k = tid; k < KD * OWW; k += NT) {
            int i = k / OWW, ow = k - i * OWW;
            int c2 = 2 * ow + i - MD;
            int m2 = ow >> 3;
            int cs2 = min(max(16 * m2 - 24, 0), 32);
            const float* Cm = reinterpret_cast<const float*>(smc + SCB + m2 * CBPL);
            int r0 = (2 * ow) & 15;
            float v = 0.f;
            if ((unsigned)c2 < 96u)       v += Cm[r0 * CBST + c2 - cs2];
            if ((unsigned)(c2 + 1) < 96u) v += Cm[(r0 + 1) * CBST + c2 + 1 - cs2];
            outg[(((size_t)b * (KD * KD) + i * KD + jglob) * OHH + oh) * OWW + ow] =
                v * (1.0f / 512.0f);
        }
        __syncthreads();
    }
}

extern "C" void kernel_launch(void* const* d_in, const int* in_sizes, int n_in,
                              void* d_out, int out_size)
{
    (void)in_sizes; (void)n_in; (void)out_size;
    const float* x1 = (const float*)d_in[0];
    const float* x2 = (const float*)d_in[1];
    float* out = (float*)d_out;

    static bool attr_set = false;
    if (!attr_set) {
        cudaFuncSetAttribute(cvt_kernel, cudaFuncAttributeMaxDynamicSharedMemorySize,
                             CHAN * CVT_S * (int)sizeof(float));
        cudaFuncSetAttribute(corr_hmma_kernel, cudaFuncAttributeMaxDynamicSharedMemorySize,
                             SMEM_MAIN);
        attr_set = true;
    }
    cvt_kernel<<<dim3(HH, BATCH, 2), 256, CHAN * CVT_S * sizeof(float)>>>(x1, x2);
    corr_hmma_kernel<<<dim3(2, OHH, BATCH), NT, SMEM_MAIN>>>(out);
}

// round 6
// speedup vs baseline: 4.7515x; 1.2994x over previous
#include <cuda_runtime.h>
#include <cuda_fp16.h>
#include <cstdint>
#include <cstddef>

#define BATCH 4
#define CHAN  128
#define HH    96
#define WW    96
#define MD    20
#define KD    41
#define OHH   48
#define OWW   48

// fp16 channel-last staging: x[b][h][w][ch]
__device__ __half x1t_g[BATCH * HH * WW * CHAN];
__device__ __half x2t_g[BATCH * HH * WW * CHAN];

// ---------- prepass: fp32 [b][ch][h][w] -> fp16 [b][h][w][ch] ----------
// smem: half2 hsm[w*65 + cp] (stride 65 -> conflict-free both phases)
__global__ void __launch_bounds__(256, 4)
cvt_kernel(const float* __restrict__ x1, const float* __restrict__ x2)
{
    __shared__ __half2 hsm[WW * 65];
    const int h = blockIdx.x, b = blockIdx.y;
    const float* src = (blockIdx.z == 0) ? x1 : x2;
    __half* dst = (blockIdx.z == 0) ? x1t_g : x2t_g;
    const float* sp = src + ((size_t)b * CHAN) * (HH * WW) + (size_t)h * WW;
    // read: lane-consecutive w -> coalesced LDG; STS stride 65 words -> no conflict
    for (int idx = threadIdx.x; idx < (CHAN / 2) * WW; idx += 256) {
        int cp = idx / WW, w = idx - cp * WW;
        float v0 = sp[(size_t)(2 * cp) * (HH * WW) + w];
        float v1 = sp[(size_t)(2 * cp + 1) * (HH * WW) + w];
        hsm[w * 65 + cp] = __floats2half2_rn(v0, v1);
    }
    __syncthreads();
    // write: consecutive cp -> conflict-free LDS + coalesced STG
    __half2* dp = reinterpret_cast<__half2*>(dst + ((size_t)(b * HH + h)) * WW * CHAN);
    for (int idx = threadIdx.x; idx < WW * (CHAN / 2); idx += 256) {
        int w = idx >> 6, cp = idx & 63;
        dp[w * (CHAN / 2) + cp] = hsm[w * 65 + cp];
    }
}

// ---------- main kernel ----------
#define NT     384
#define SLAB   24576                     // 96 rows x 256B
#define SA0    0
#define SA1    SLAB
#define SB     (2 * SLAB)                // 3-slot ring
#define SCB    (5 * SLAB)
#define CBST   66
#define CBPL   (16 * CBST * 4)
#define SMEM_MAIN (SCB + 6 * CBPL)       // 148224 B

__device__ __forceinline__ uint32_t smem_u32(const void* p) {
    uint32_t a;
    asm("{ .reg .u64 t; cvta.to.shared.u64 t, %1; cvt.u32.u64 %0, t; }" : "=r"(a) : "l"(p));
    return a;
}
__device__ __forceinline__ void cpa16(uint32_t dst, const void* src, uint32_t sz) {
    asm volatile("cp.async.ca.shared.global [%0], [%1], 16, %2;"
                 :: "r"(dst), "l"(src), "r"(sz) : "memory");
}
__device__ __forceinline__ void fill_slab(uint32_t dstb, const __half* src,
                                          bool valid, int tid)
{
#pragma unroll
    for (int it = 0; it < 4; ++it) {
        int q = tid + it * NT;
        int n = q >> 4, c = q & 15;
        uint32_t dst = dstb + n * 256 + ((c ^ (n & 7)) << 4);
        cpa16(dst, src + n * CHAN + c * 8, valid ? 16u : 0u);
    }
}
__device__ __forceinline__ void ldsm4(uint32_t& r0, uint32_t& r1, uint32_t& r2,
                                      uint32_t& r3, uint32_t a) {
    asm volatile("ldmatrix.sync.aligned.m8n8.x4.shared.b16 {%0,%1,%2,%3}, [%4];"
                 : "=r"(r0), "=r"(r1), "=r"(r2), "=r"(r3) : "r"(a));
}
__device__ __forceinline__ void mma16816(float* c, uint32_t a0, uint32_t a1,
                                         uint32_t a2, uint32_t a3,
                                         uint32_t b0, uint32_t b1) {
    asm volatile("mma.sync.aligned.m16n8k16.row.col.f32.f16.f16.f32 "
                 "{%0,%1,%2,%3},{%4,%5,%6,%7},{%8,%9},{%0,%1,%2,%3};"
                 : "+f"(c[0]), "+f"(c[1]), "+f"(c[2]), "+f"(c[3])
                 : "r"(a0), "r"(a1), "r"(a2), "r"(a3), "r"(b0), "r"(b1));
}

__global__ void __launch_bounds__(NT, 1)
corr_hmma_kernel(float* __restrict__ outg)
{
    extern __shared__ char smc[];
    const uint32_t sb = smem_u32(smc);
    const int tid = threadIdx.x, warp = tid >> 5, lane = tid & 31;
    const int m = warp >> 1;
    const int nh = warp & 1;
    const int jb = blockIdx.x, oh = blockIdx.y, b = blockIdx.z;
    const int j0 = jb * 14;
    const int cnt = (jb == 2) ? 13 : 14;
    const int R0 = 2 * oh + j0 - MD;

    // ---- prolog fills: A slabs + B rows R0, R0+1 (group 0) ----
    const __half* x1b = x1t_g + ((size_t)(b * HH + 2 * oh)) * WW * CHAN;
    fill_slab(sb + SA0, x1b, true, tid);
    fill_slab(sb + SA1, x1b + WW * CHAN, true, tid);
    const __half* x2bb = x2t_g + (size_t)b * HH * WW * CHAN;
#pragma unroll
    for (int k = 0; k < 2; ++k) {
        int row = R0 + k;
        bool v = (unsigned)row < HH;
        fill_slab(sb + SB + k * SLAB, x2bb + (size_t)(v ? row : 0) * WW * CHAN, v, tid);
    }
    asm volatile("cp.async.commit_group;" ::: "memory");

    // ---- ldmatrix addressing ----
    const int cs = min(max(16 * m - 24, 0), 32);
    const int ra = m * 16 + (lane & 15);
    const uint32_t aoff = (uint32_t)(ra * 256);
    const int swa = ra & 7;
    const int ahi = lane >> 4;
    int rb0 = cs + (nh * 4 + 0 + (lane >> 4)) * 8 + (lane & 7);
    int rb1 = cs + (nh * 4 + 2 + (lane >> 4)) * 8 + (lane & 7);
    const uint32_t boff0 = (uint32_t)(rb0 * 256);
    const uint32_t boff1 = (uint32_t)(rb1 * 256);
    const int swb0 = rb0 & 7, swb1 = rb1 & 7;
    const int bhi = (lane >> 3) & 1;

    // ---- load A fragments into registers ONCE ----
    asm volatile("cp.async.wait_group 0;" ::: "memory");
    __syncthreads();
    uint32_t aR[2][8][4];
#pragma unroll
    for (int h = 0; h < 2; ++h) {
        const uint32_t ab = sb + (h ? SA1 : SA0) + aoff;
#pragma unroll
        for (int ks = 0; ks < 8; ++ks)
            ldsm4(aR[h][ks][0], aR[h][ks][1], aR[h][ks][2], aR[h][ks][3],
                  ab + (((2 * ks + ahi) ^ swa) << 4));
    }

    float* Cbm = reinterpret_cast<float*>(smc + SCB + m * CBPL);
    const int gr = lane >> 2, ccl = 2 * (lane & 3);

    for (int l = 0; l < cnt; ++l) {
        // prefetch B row R0+l+2 into slot (l+2)%3
        if (l + 2 <= cnt) {
            int row = R0 + l + 2;
            bool v = (unsigned)row < HH;
            fill_slab(sb + SB + ((l + 2) % 3) * SLAB,
                      x2bb + (size_t)(v ? row : 0) * WW * CHAN, v, tid);
        }
        asm volatile("cp.async.commit_group;" ::: "memory");
        asm volatile("cp.async.wait_group 1;" ::: "memory");
        __syncthreads();

        float acc[4][4];
#pragma unroll
        for (int t = 0; t < 4; ++t)
#pragma unroll
            for (int q = 0; q < 4; ++q) acc[t][q] = 0.f;

#pragma unroll
        for (int h = 0; h < 2; ++h) {
            const uint32_t bb = sb + SB + (uint32_t)(((l + h) % 3) * SLAB);
#pragma unroll
            for (int ks = 0; ks < 8; ++ks) {
                uint32_t b0, b1, b2, b3;
                ldsm4(b0, b1, b2, b3, bb + boff0 + (((2 * ks + bhi) ^ swb0) << 4));
                mma16816(acc[0], aR[h][ks][0], aR[h][ks][1], aR[h][ks][2], aR[h][ks][3], b0, b1);
                mma16816(acc[1], aR[h][ks][0], aR[h][ks][1], aR[h][ks][2], aR[h][ks][3], b2, b3);
                ldsm4(b0, b1, b2, b3, bb + boff1 + (((2 * ks + bhi) ^ swb1) << 4));
                mma16816(acc[2], aR[h][ks][0], aR[h][ks][1], aR[h][ks][2], aR[h][ks][3], b0, b1);
                mma16816(acc[3], aR[h][ks][0], aR[h][ks][1], aR[h][ks][2], aR[h][ks][3], b2, b3);
            }
        }

        // spill band patch
#pragma unroll
        for (int t = 0; t < 4; ++t) {
            int n = nh * 4 + t;
            *reinterpret_cast<float2*>(Cbm + gr * CBST + n * 8 + ccl) =
                make_float2(acc[t][0], acc[t][1]);
            *reinterpret_cast<float2*>(Cbm + (gr + 8) * CBST + n * 8 + ccl) =
                make_float2(acc[t][2], acc[t][3]);
        }
        __syncthreads();

        // banded gather -> out
        const int jglob = j0 + l;
        for (int k = tid; k < KD * OWW; k += NT) {
            int i = k / OWW, ow = k - i * OWW;
            int c2 = 2 * ow + i - MD;
            int m2 = ow >> 3;
            int cs2 = min(max(16 * m2 - 24, 0), 32);
            const float* Cm = reinterpret_cast<const float*>(smc + SCB + m2 * CBPL);
            int r0 = (2 * ow) & 15;
            float v = 0.f;
            if ((unsigned)c2 < 96u)       v += Cm[r0 * CBST + c2 - cs2];
            if ((unsigned)(c2 + 1) < 96u) v += Cm[(r0 + 1) * CBST + c2 + 1 - cs2];
            outg[(((size_t)b * (KD * KD) + i * KD + jglob) * OHH + oh) * OWW + ow] =
                v * (1.0f / 512.0f);
        }
        __syncthreads();
    }
}

extern "C" void kernel_launch(void* const* d_in, const int* in_sizes, int n_in,
                              void* d_out, int out_size)
{
    (void)in_sizes; (void)n_in; (void)out_size;
    const float* x1 = (const float*)d_in[0];
    const float* x2 = (const float*)d_in[1];
    float* out = (float*)d_out;

    static bool attr_set = false;
    if (!attr_set) {
        cudaFuncSetAttribute(corr_hmma_kernel, cudaFuncAttributeMaxDynamicSharedMemorySize,
                             SMEM_MAIN);
        attr_set = true;
    }
    cvt_kernel<<<dim3(HH, BATCH, 2), 256>>>(x1, x2);
    corr_hmma_kernel<<<dim3(3, OHH, BATCH), NT, SMEM_MAIN>>>(out);
}

// round 7
// speedup vs baseline: 5.4395x; 1.1448x over previous
#include <cuda_runtime.h>
#include <cuda_fp16.h>
#include <cstdint>
#include <cstddef>

#define BATCH 4
#define CHAN  128
#define HH    96
#define WW    96
#define MD    20
#define KD    41
#define OHH   48
#define OWW   48

// fp16 channel-last staging: x[b][h][w][ch]
__device__ __half x1t_g[BATCH * HH * WW * CHAN];
__device__ __half x2t_g[BATCH * HH * WW * CHAN];

// ---------- prepass: fp32 [b][ch][h][w] -> fp16 [b][h][w][ch] ----------
__global__ void __launch_bounds__(256, 4)
cvt_kernel(const float* __restrict__ x1, const float* __restrict__ x2)
{
    __shared__ __half2 hsm[WW * 65];
    const int h = blockIdx.x, b = blockIdx.y;
    const float* src = (blockIdx.z == 0) ? x1 : x2;
    __half* dst = (blockIdx.z == 0) ? x1t_g : x2t_g;
    const float* sp = src + ((size_t)b * CHAN) * (HH * WW) + (size_t)h * WW;
    for (int idx = threadIdx.x; idx < (CHAN / 2) * WW; idx += 256) {
        int cp = idx / WW, w = idx - cp * WW;
        float v0 = sp[(size_t)(2 * cp) * (HH * WW) + w];
        float v1 = sp[(size_t)(2 * cp + 1) * (HH * WW) + w];
        hsm[w * 65 + cp] = __floats2half2_rn(v0, v1);
    }
    __syncthreads();
    __half2* dp = reinterpret_cast<__half2*>(dst + ((size_t)(b * HH + h)) * WW * CHAN);
    for (int idx = threadIdx.x; idx < WW * (CHAN / 2); idx += 256) {
        int w = idx >> 6, cp = idx & 63;
        dp[w * (CHAN / 2) + cp] = hsm[w * 65 + cp];
    }
}

// ---------- main kernel ----------
#define NT     384
#define SLAB   24576                     // 96 rows x 256B
#define SA0    0
#define SA1    SLAB
#define SB     (2 * SLAB)                // 3-slot B ring
#define SCB    (5 * SLAB)
#define CBST   66
#define CBPL   (16 * CBST * 4)
#define SMEM_MAIN (SCB + 6 * CBPL)       // 148224 B

__device__ __forceinline__ uint32_t smem_u32(const void* p) {
    uint32_t a;
    asm("{ .reg .u64 t; cvta.to.shared.u64 t, %1; cvt.u32.u64 %0, t; }" : "=r"(a) : "l"(p));
    return a;
}
__device__ __forceinline__ void cpa16(uint32_t dst, const void* src, uint32_t sz) {
    asm volatile("cp.async.ca.shared.global [%0], [%1], 16, %2;"
                 :: "r"(dst), "l"(src), "r"(sz) : "memory");
}
__device__ __forceinline__ void fill_slab(uint32_t dstb, const __half* src,
                                          bool valid, int tid)
{
#pragma unroll
    for (int it = 0; it < 4; ++it) {
        int q = tid + it * NT;
        int n = q >> 4, c = q & 15;
        uint32_t dst = dstb + n * 256 + ((c ^ (n & 7)) << 4);
        cpa16(dst, src + n * CHAN + c * 8, valid ? 16u : 0u);
    }
}
__device__ __forceinline__ void ldsm4(uint32_t& r0, uint32_t& r1, uint32_t& r2,
                                      uint32_t& r3, uint32_t a) {
    asm volatile("ldmatrix.sync.aligned.m8n8.x4.shared.b16 {%0,%1,%2,%3}, [%4];"
                 : "=r"(r0), "=r"(r1), "=r"(r2), "=r"(r3) : "r"(a));
}
__device__ __forceinline__ void mma16816(float* c, const uint32_t* a,
                                         uint32_t b0, uint32_t b1) {
    asm volatile("mma.sync.aligned.m16n8k16.row.col.f32.f16.f16.f32 "
                 "{%0,%1,%2,%3},{%4,%5,%6,%7},{%8,%9},{%0,%1,%2,%3};"
                 : "+f"(c[0]), "+f"(c[1]), "+f"(c[2]), "+f"(c[3])
                 : "r"(a[0]), "r"(a[1]), "r"(a[2]), "r"(a[3]), "r"(b0), "r"(b1));
}

__global__ void __launch_bounds__(NT, 1)
corr_hmma_kernel(float* __restrict__ outg)
{
    extern __shared__ char smc[];
    const uint32_t sb = smem_u32(smc);
    const int tid = threadIdx.x, warp = tid >> 5, lane = tid & 31;
    const int m = warp >> 1;
    const int nh = warp & 1;
    const int jb = blockIdx.x, oh = blockIdx.y, b = blockIdx.z;
    const int j0 = jb * 14;
    const int cnt = (jb == 2) ? 13 : 14;   // j count; rows used: R0 .. R0+cnt
    const int R0 = 2 * oh + j0 - MD;

    // ---- prolog fills: A slabs + B rows R0, R0+1 ----
    const __half* x1b = x1t_g + ((size_t)(b * HH + 2 * oh)) * WW * CHAN;
    fill_slab(sb + SA0, x1b, true, tid);
    fill_slab(sb + SA1, x1b + WW * CHAN, true, tid);
    const __half* x2bb = x2t_g + (size_t)b * HH * WW * CHAN;
#pragma unroll
    for (int k = 0; k < 2; ++k) {
        int row = R0 + k;
        bool v = (unsigned)row < HH;
        fill_slab(sb + SB + k * SLAB, x2bb + (size_t)(v ? row : 0) * WW * CHAN, v, tid);
    }
    asm volatile("cp.async.commit_group;" ::: "memory");

    // ---- ldmatrix addressing ----
    const int cs = min(max(16 * m - 24, 0), 32);
    const int ra = m * 16 + (lane & 15);
    const uint32_t aoff = (uint32_t)(ra * 256);
    const int swa = ra & 7;
    const int ahi = lane >> 4;
    int rb0 = cs + (nh * 4 + 0 + (lane >> 4)) * 8 + (lane & 7);
    int rb1 = cs + (nh * 4 + 2 + (lane >> 4)) * 8 + (lane & 7);
    const uint32_t boff0 = (uint32_t)(rb0 * 256);
    const uint32_t boff1 = (uint32_t)(rb1 * 256);
    const int swb0 = rb0 & 7, swb1 = rb1 & 7;
    const int bhi = (lane >> 3) & 1;

    // ---- hoist A fragments (once per CTA) ----
    asm volatile("cp.async.wait_group 0;" ::: "memory");
    __syncthreads();
    uint32_t aR[2][8][4];
#pragma unroll
    for (int h = 0; h < 2; ++h) {
        const uint32_t ab = sb + (h ? SA1 : SA0) + aoff;
#pragma unroll
        for (int ks = 0; ks < 8; ++ks)
            ldsm4(aR[h][ks][0], aR[h][ks][1], aR[h][ks][2], aR[h][ks][3],
                  ab + (((2 * ks + ahi) ^ swa) << 4));
    }

    float* Cbm = reinterpret_cast<float*>(smc + SCB + m * CBPL);
    const int gr = lane >> 2, ccl = 2 * (lane & 3);

    // two live accumulator sets: accP = GEMM(j0+l-1), accC = GEMM(j0+l)
    float accP[4][4], accC[4][4];
#pragma unroll
    for (int t = 0; t < 4; ++t)
#pragma unroll
        for (int q = 0; q < 4; ++q) { accP[t][q] = 0.f; accC[t][q] = 0.f; }

    // row-pipelined loop: iteration l consumes B row R0+l exactly once
    for (int l = 0; l <= cnt; ++l) {
        // row l ready when <=1 groups pending (last commit = row l+1's fill)
        asm volatile("cp.async.wait_group 1;" ::: "memory");
        __syncthreads();
        // prefetch row R0+l+2 into slot (l+2)%3 (slot last read at iter l-1)
        if (l + 2 <= cnt) {
            int row = R0 + l + 2;
            bool v = (unsigned)row < HH;
            fill_slab(sb + SB + ((l + 2) % 3) * SLAB,
                      x2bb + (size_t)(v ? row : 0) * WW * CHAN, v, tid);
        }
        asm volatile("cp.async.commit_group;" ::: "memory");

        // ---- consume B row l: feed accP (K-half 1) and accC (K-half 0) ----
        const uint32_t bb = sb + SB + (uint32_t)((l % 3) * SLAB);
        const bool doP = (l > 0), doC = (l < cnt);
#pragma unroll
        for (int ks = 0; ks < 8; ++ks) {
            uint32_t b0, b1, b2, b3;
            ldsm4(b0, b1, b2, b3, bb + boff0 + (((2 * ks + bhi) ^ swb0) << 4));
            if (doP) { mma16816(accP[0], aR[1][ks], b0, b1);
                       mma16816(accP[1], aR[1][ks], b2, b3); }
            if (doC) { mma16816(accC[0], aR[0][ks], b0, b1);
                       mma16816(accC[1], aR[0][ks], b2, b3); }
            ldsm4(b0, b1, b2, b3, bb + boff1 + (((2 * ks + bhi) ^ swb1) << 4));
            if (doP) { mma16816(accP[2], aR[1][ks], b0, b1);
                       mma16816(accP[3], aR[1][ks], b2, b3); }
            if (doC) { mma16816(accC[2], aR[0][ks], b0, b1);
                       mma16816(accC[3], aR[0][ks], b2, b3); }
        }

        // ---- retire accP = GEMM(j0+l-1) ----
        if (l > 0) {
#pragma unroll
            for (int t = 0; t < 4; ++t) {
                int n = nh * 4 + t;
                *reinterpret_cast<float2*>(Cbm + gr * CBST + n * 8 + ccl) =
                    make_float2(accP[t][0], accP[t][1]);
                *reinterpret_cast<float2*>(Cbm + (gr + 8) * CBST + n * 8 + ccl) =
                    make_float2(accP[t][2], accP[t][3]);
            }
            __syncthreads();
            const int jglob = j0 + l - 1;
            for (int k = tid; k < KD * OWW; k += NT) {
                int i = k / OWW, ow = k - i * OWW;
                int c2 = 2 * ow + i - MD;
                int m2 = ow >> 3;
                int cs2 = min(max(16 * m2 - 24, 0), 32);
                const float* Cm = reinterpret_cast<const float*>(smc + SCB + m2 * CBPL);
                int r0 = (2 * ow) & 15;
                float v = 0.f;
                if ((unsigned)c2 < 96u)       v += Cm[r0 * CBST + c2 - cs2];
                if ((unsigned)(c2 + 1) < 96u) v += Cm[(r0 + 1) * CBST + c2 + 1 - cs2];
                outg[(((size_t)b * (KD * KD) + i * KD + jglob) * OHH + oh) * OWW + ow] =
                    v * (1.0f / 512.0f);
            }
        }
        // rotate accumulators: accP <- accC, accC <- 0
#pragma unroll
        for (int t = 0; t < 4; ++t)
#pragma unroll
            for (int q = 0; q < 4; ++q) { accP[t][q] = accC[t][q]; accC[t][q] = 0.f; }
    }
}

extern "C" void kernel_launch(void* const* d_in, const int* in_sizes, int n_in,
                              void* d_out, int out_size)
{
    (void)in_sizes; (void)n_in; (void)out_size;
    const float* x1 = (const float*)d_in[0];
    const float* x2 = (const float*)d_in[1];
    float* out = (float*)d_out;

    static bool attr_set = false;
    if (!attr_set) {
        cudaFuncSetAttribute(corr_hmma_kernel, cudaFuncAttributeMaxDynamicSharedMemorySize,
                             SMEM_MAIN);
        attr_set = true;
    }
    cvt_kernel<<<dim3(HH, BATCH, 2), 256>>>(x1, x2);
    corr_hmma_kernel<<<dim3(3, OHH, BATCH), NT, SMEM_MAIN>>>(out);
}

// round 8
// speedup vs baseline: 5.4487x; 1.0017x over previous
#include <cuda_runtime.h>
#include <cuda_fp16.h>
#include <cstdint>
#include <cstddef>

#define BATCH 4
#define CHAN  128
#define HH    96
#define WW    96
#define MD    20
#define KD    41
#define OHH   48
#define OWW   48

// fp16 channel-last staging: x[b][h][w][ch]
__device__ __half x1t_g[BATCH * HH * WW * CHAN];
__device__ __half x2t_g[BATCH * HH * WW * CHAN];

// ---------- prepass: fp32 [b][ch][h][w] -> fp16 [b][h][w][ch] ----------
__global__ void __launch_bounds__(256, 4)
cvt_kernel(const float* __restrict__ x1, const float* __restrict__ x2)
{
    __shared__ __half2 hsm[WW * 65];
    const int h = blockIdx.x, b = blockIdx.y;
    const float* src = (blockIdx.z == 0) ? x1 : x2;
    __half* dst = (blockIdx.z == 0) ? x1t_g : x2t_g;
    const float* sp = src + ((size_t)b * CHAN) * (HH * WW) + (size_t)h * WW;
    for (int idx = threadIdx.x; idx < (CHAN / 2) * WW; idx += 256) {
        int cp = idx / WW, w = idx - cp * WW;
        float v0 = sp[(size_t)(2 * cp) * (HH * WW) + w];
        float v1 = sp[(size_t)(2 * cp + 1) * (HH * WW) + w];
        hsm[w * 65 + cp] = __floats2half2_rn(v0, v1);
    }
    __syncthreads();
    __half2* dp = reinterpret_cast<__half2*>(dst + ((size_t)(b * HH + h)) * WW * CHAN);
    for (int idx = threadIdx.x; idx < WW * (CHAN / 2); idx += 256) {
        int w = idx >> 6, cp = idx & 63;
        dp[w * (CHAN / 2) + cp] = hsm[w * 65 + cp];
    }
}

// ---------- main kernel ----------
#define NT     384
#define SLAB   24576                     // 96 rows x 256B
#define SA0    0
#define SA1    SLAB
#define SB     (2 * SLAB)                // 3-slot B ring
#define SCB    (5 * SLAB)
#define CBST   66
#define CBPL   (16 * CBST * 4)
#define SMEM_MAIN (SCB + 6 * CBPL)       // 148224 B

__device__ __forceinline__ uint32_t smem_u32(const void* p) {
    uint32_t a;
    asm("{ .reg .u64 t; cvta.to.shared.u64 t, %1; cvt.u32.u64 %0, t; }" : "=r"(a) : "l"(p));
    return a;
}
__device__ __forceinline__ void cpa16(uint32_t dst, const void* src, uint32_t sz) {
    asm volatile("cp.async.ca.shared.global [%0], [%1], 16, %2;"
                 :: "r"(dst), "l"(src), "r"(sz) : "memory");
}
__device__ __forceinline__ void fill_slab(uint32_t dstb, const __half* src,
                                          bool valid, int tid)
{
#pragma unroll
    for (int it = 0; it < 4; ++it) {
        int q = tid + it * NT;
        int n = q >> 4, c = q & 15;
        uint32_t dst = dstb + n * 256 + ((c ^ (n & 7)) << 4);
        cpa16(dst, src + n * CHAN + c * 8, valid ? 16u : 0u);
    }
}
__device__ __forceinline__ void ldsm4(uint32_t& r0, uint32_t& r1, uint32_t& r2,
                                      uint32_t& r3, uint32_t a) {
    asm volatile("ldmatrix.sync.aligned.m8n8.x4.shared.b16 {%0,%1,%2,%3}, [%4];"
                 : "=r"(r0), "=r"(r1), "=r"(r2), "=r"(r3) : "r"(a));
}
__device__ __forceinline__ void mma16816(float* c, const uint32_t* a,
                                         uint32_t b0, uint32_t b1) {
    asm volatile("mma.sync.aligned.m16n8k16.row.col.f32.f16.f16.f32 "
                 "{%0,%1,%2,%3},{%4,%5,%6,%7},{%8,%9},{%0,%1,%2,%3};"
                 : "+f"(c[0]), "+f"(c[1]), "+f"(c[2]), "+f"(c[3])
                 : "r"(a[0]), "r"(a[1]), "r"(a[2]), "r"(a[3]), "r"(b0), "r"(b1));
}

template <bool DOP, bool DOC>
__device__ __forceinline__ void mma_row(uint32_t bb, uint32_t boff0, uint32_t boff1,
                                        int swb0, int swb1, int bhi,
                                        const uint32_t aR[2][8][4],
                                        float accP[4][4], float accC[4][4])
{
#pragma unroll
    for (int ks = 0; ks < 8; ++ks) {
        uint32_t b0, b1, b2, b3;
        ldsm4(b0, b1, b2, b3, bb + boff0 + (((2 * ks + bhi) ^ swb0) << 4));
        if (DOP) { mma16816(accP[0], aR[1][ks], b0, b1);
                   mma16816(accP[1], aR[1][ks], b2, b3); }
        if (DOC) { mma16816(accC[0], aR[0][ks], b0, b1);
                   mma16816(accC[1], aR[0][ks], b2, b3); }
        ldsm4(b0, b1, b2, b3, bb + boff1 + (((2 * ks + bhi) ^ swb1) << 4));
        if (DOP) { mma16816(accP[2], aR[1][ks], b0, b1);
                   mma16816(accP[3], aR[1][ks], b2, b3); }
        if (DOC) { mma16816(accC[2], aR[0][ks], b0, b1);
                   mma16816(accC[3], aR[0][ks], b2, b3); }
    }
}

__global__ void __launch_bounds__(NT, 1)
corr_hmma_kernel(float* __restrict__ outg)
{
    extern __shared__ char smc[];
    const uint32_t sb = smem_u32(smc);
    const int tid = threadIdx.x, warp = tid >> 5, lane = tid & 31;
    const int m = warp >> 1;
    const int nh = warp & 1;
    const int jb = blockIdx.x, oh = blockIdx.y, b = blockIdx.z;
    const int j0 = jb * 14;
    const int cnt = (jb == 2) ? 13 : 14;   // rows used: R0 .. R0+cnt
    const int R0 = 2 * oh + j0 - MD;

    // ---- prolog fills: A slabs + B rows R0, R0+1 ----
    const __half* x1b = x1t_g + ((size_t)(b * HH + 2 * oh)) * WW * CHAN;
    fill_slab(sb + SA0, x1b, true, tid);
    fill_slab(sb + SA1, x1b + WW * CHAN, true, tid);
    const __half* x2bb = x2t_g + (size_t)b * HH * WW * CHAN;
#pragma unroll
    for (int k = 0; k < 2; ++k) {
        int row = R0 + k;
        bool v = (unsigned)row < HH;
        fill_slab(sb + SB + k * SLAB, x2bb + (size_t)(v ? row : 0) * WW * CHAN, v, tid);
    }
    asm volatile("cp.async.commit_group;" ::: "memory");

    // ---- ldmatrix addressing ----
    const int cs = min(max(16 * m - 24, 0), 32);
    const int ra = m * 16 + (lane & 15);
    const uint32_t aoff = (uint32_t)(ra * 256);
    const int swa = ra & 7;
    const int ahi = lane >> 4;
    int rb0 = cs + (nh * 4 + 0 + (lane >> 4)) * 8 + (lane & 7);
    int rb1 = cs + (nh * 4 + 2 + (lane >> 4)) * 8 + (lane & 7);
    const uint32_t boff0 = (uint32_t)(rb0 * 256);
    const uint32_t boff1 = (uint32_t)(rb1 * 256);
    const int swb0 = rb0 & 7, swb1 = rb1 & 7;
    const int bhi = (lane >> 3) & 1;

    // ---- epilogue closed-form precompute (j- and s-invariant parts) ----
    // k = tid + s*384, 384 = 8*48 -> ow = tid%48 (s-invariant), i = tid/48 + 8s
    const int owg = tid % 48;
    const int i0g = tid / 48;
    const int m2  = owg >> 3;
    const int cs2 = min(max(16 * m2 - 24, 0), 32);
    const int r0g = (2 * owg) & 15;
    const int c2b = 2 * owg + i0g - MD;
    float* CmT = reinterpret_cast<float*>(smc + SCB + m2 * CBPL) + r0g * CBST - cs2;
    float* zp  = reinterpret_cast<float*>(smc + SCB) + 64;   // zeroed pad word
    const size_t ob = ((size_t)b * (KD * KD) + (size_t)i0g * KD) * (OHH * OWW)
                      + (size_t)oh * OWW + owg;

    // zero Cbuf pad columns 64,65 (never written by spill)
    if (tid < 192) {
        int plane = tid >> 5, rem = tid & 31;
        reinterpret_cast<float*>(smc + SCB + plane * CBPL)[(rem >> 1) * CBST + 64 + (rem & 1)] = 0.f;
    }

    // ---- hoist A fragments (once per CTA) ----
    asm volatile("cp.async.wait_group 0;" ::: "memory");
    __syncthreads();
    uint32_t aR[2][8][4];
#pragma unroll
    for (int h = 0; h < 2; ++h) {
        const uint32_t ab = sb + (h ? SA1 : SA0) + aoff;
#pragma unroll
        for (int ks = 0; ks < 8; ++ks)
            ldsm4(aR[h][ks][0], aR[h][ks][1], aR[h][ks][2], aR[h][ks][3],
                  ab + (((2 * ks + ahi) ^ swa) << 4));
    }

    float* Cbm = reinterpret_cast<float*>(smc + SCB + m * CBPL);
    const int gr = lane >> 2, ccl = 2 * (lane & 3);

    float accP[4][4], accC[4][4];
#pragma unroll
    for (int t = 0; t < 4; ++t)
#pragma unroll
        for (int q = 0; q < 4; ++q) { accP[t][q] = 0.f; accC[t][q] = 0.f; }

    for (int l = 0; l <= cnt; ++l) {
        asm volatile("cp.async.wait_group 1;" ::: "memory");
        __syncthreads();
        if (l + 2 <= cnt) {
            int row = R0 + l + 2;
            bool v = (unsigned)row < HH;
            fill_slab(sb + SB + ((l + 2) % 3) * SLAB,
                      x2bb + (size_t)(v ? row : 0) * WW * CHAN, v, tid);
        }
        asm volatile("cp.async.commit_group;" ::: "memory");

        const uint32_t bb = sb + SB + (uint32_t)((l % 3) * SLAB);
        if (l == 0)
            mma_row<false, true >(bb, boff0, boff1, swb0, swb1, bhi, aR, accP, accC);
        else if (l == cnt)
            mma_row<true , false>(bb, boff0, boff1, swb0, swb1, bhi, aR, accP, accC);
        else
            mma_row<true , true >(bb, boff0, boff1, swb0, swb1, bhi, aR, accP, accC);

        if (l > 0) {
            // spill accP = GEMM(j0+l-1)
#pragma unroll
            for (int t = 0; t < 4; ++t) {
                int n = nh * 4 + t;
                *reinterpret_cast<float2*>(Cbm + gr * CBST + n * 8 + ccl) =
                    make_float2(accP[t][0], accP[t][1]);
                *reinterpret_cast<float2*>(Cbm + (gr + 8) * CBST + n * 8 + ccl) =
                    make_float2(accP[t][2], accP[t][3]);
            }
            __syncthreads();
            // banded gather -> out (closed-form addressing)
            float* op = outg + ob + (size_t)(j0 + l - 1) * (OHH * OWW);
#pragma unroll
            for (int s = 0; s < 6; ++s) {
                if (s == 5 && tid >= 48) break;
                int c2 = c2b + 8 * s;
                const float* p0 = ((unsigned)c2 < 96u) ? (CmT + c2) : zp;
                const float* p1 = ((unsigned)(c2 + 1) < 96u) ? (CmT + c2 + CBST + 1) : zp;
                op[(size_t)s * (8 * KD * OHH * OWW)] = (*p0 + *p1) * (1.0f / 512.0f);
            }
        }
#pragma unroll
        for (int t = 0; t < 4; ++t)
#pragma unroll
            for (int q = 0; q < 4; ++q) { accP[t][q] = accC[t][q]; accC[t][q] = 0.f; }
    }
}

extern "C" void kernel_launch(void* const* d_in, const int* in_sizes, int n_in,
                              void* d_out, int out_size)
{
    (void)in_sizes; (void)n_in; (void)out_size;
    const float* x1 = (const float*)d_in[0];
    const float* x2 = (const float*)d_in[1];
    float* out = (float*)d_out;

    static bool attr_set = false;
    if (!attr_set) {
        cudaFuncSetAttribute(corr_hmma_kernel, cudaFuncAttributeMaxDynamicSharedMemorySize,
                             SMEM_MAIN);
        attr_set = true;
    }
    cvt_kernel<<<dim3(HH, BATCH, 2), 256>>>(x1, x2);
    corr_hmma_kernel<<<dim3(3, OHH, BATCH), NT, SMEM_MAIN>>>(out);
}

// round 9
// speedup vs baseline: 5.4627x; 1.0026x over previous
#include <cuda_runtime.h>
#include <cuda_fp16.h>
#include <cstdint>
#include <cstddef>

#define BATCH 4
#define CHAN  128
#define HH    96
#define WW    96
#define MD    20
#define KD    41
#define OHH   48
#define OWW   48

// fp16 channel-last staging: x[b][h][w][ch]
__device__ __half x1t_g[BATCH * HH * WW * CHAN];
__device__ __half x2t_g[BATCH * HH * WW * CHAN];

// ---------- prepass: fp32 [b][ch][h][w] -> fp16 [b][h][w][ch] ----------
__global__ void __launch_bounds__(256, 4)
cvt_kernel(const float* __restrict__ x1, const float* __restrict__ x2)
{
    __shared__ __half2 hsm[WW * 65];
    const int h = blockIdx.x, b = blockIdx.y;
    const float* src = (blockIdx.z == 0) ? x1 : x2;
    __half* dst = (blockIdx.z == 0) ? x1t_g : x2t_g;
    const float* sp = src + ((size_t)b * CHAN) * (HH * WW) + (size_t)h * WW;
    for (int idx = threadIdx.x; idx < (CHAN / 2) * WW; idx += 256) {
        int cp = idx / WW, w = idx - cp * WW;
        float v0 = sp[(size_t)(2 * cp) * (HH * WW) + w];
        float v1 = sp[(size_t)(2 * cp + 1) * (HH * WW) + w];
        hsm[w * 65 + cp] = __floats2half2_rn(v0, v1);
    }
    __syncthreads();
    __half2* dp = reinterpret_cast<__half2*>(dst + ((size_t)(b * HH + h)) * WW * CHAN);
    for (int idx = threadIdx.x; idx < WW * (CHAN / 2); idx += 256) {
        int w = idx >> 6, cp = idx & 63;
        dp[w * (CHAN / 2) + cp] = hsm[w * 65 + cp];
    }
}

// ---------- main kernel ----------
#define NT     384
#define SLAB   24576                     // 96 rows x 256B
#define SA0    0
#define SA1    SLAB
#define SB     (2 * SLAB)                // 3-slot B ring
#define SCB    (5 * SLAB)
#define CBST   66
#define CBPL   (16 * CBST * 4)           // 4224 B per plane
#define CBUF   (6 * CBPL)                // 25344 B per C buffer
#define SMEM_MAIN (SCB + 2 * CBUF)       // 173568 B

__device__ __forceinline__ uint32_t smem_u32(const void* p) {
    uint32_t a;
    asm("{ .reg .u64 t; cvta.to.shared.u64 t, %1; cvt.u32.u64 %0, t; }" : "=r"(a) : "l"(p));
    return a;
}
__device__ __forceinline__ void cpa16(uint32_t dst, const void* src, uint32_t sz) {
    asm volatile("cp.async.ca.shared.global [%0], [%1], 16, %2;"
                 :: "r"(dst), "l"(src), "r"(sz) : "memory");
}
__device__ __forceinline__ void fill_slab(uint32_t dstb, const __half* src,
                                          bool valid, int tid)
{
#pragma unroll
    for (int it = 0; it < 4; ++it) {
        int q = tid + it * NT;
        int n = q >> 4, c = q & 15;
        uint32_t dst = dstb + n * 256 + ((c ^ (n & 7)) << 4);
        cpa16(dst, src + n * CHAN + c * 8, valid ? 16u : 0u);
    }
}
__device__ __forceinline__ void ldsm4(uint32_t& r0, uint32_t& r1, uint32_t& r2,
                                      uint32_t& r3, uint32_t a) {
    asm volatile("ldmatrix.sync.aligned.m8n8.x4.shared.b16 {%0,%1,%2,%3}, [%4];"
                 : "=r"(r0), "=r"(r1), "=r"(r2), "=r"(r3) : "r"(a));
}
__device__ __forceinline__ void mma16816(float* c, const uint32_t* a,
                                         uint32_t b0, uint32_t b1) {
    asm volatile("mma.sync.aligned.m16n8k16.row.col.f32.f16.f16.f32 "
                 "{%0,%1,%2,%3},{%4,%5,%6,%7},{%8,%9},{%0,%1,%2,%3};"
                 : "+f"(c[0]), "+f"(c[1]), "+f"(c[2]), "+f"(c[3])
                 : "r"(a[0]), "r"(a[1]), "r"(a[2]), "r"(a[3]), "r"(b0), "r"(b1));
}

template <bool DOP, bool DOC>
__device__ __forceinline__ void mma_row(uint32_t bb, uint32_t boff0, uint32_t boff1,
                                        int swb0, int swb1, int bhi,
                                        const uint32_t aR[2][8][4],
                                        float accP[4][4], float accC[4][4])
{
#pragma unroll
    for (int ks = 0; ks < 8; ++ks) {
        uint32_t b0, b1, b2, b3;
        ldsm4(b0, b1, b2, b3, bb + boff0 + (((2 * ks + bhi) ^ swb0) << 4));
        if (DOP) { mma16816(accP[0], aR[1][ks], b0, b1);
                   mma16816(accP[1], aR[1][ks], b2, b3); }
        if (DOC) { mma16816(accC[0], aR[0][ks], b0, b1);
                   mma16816(accC[1], aR[0][ks], b2, b3); }
        ldsm4(b0, b1, b2, b3, bb + boff1 + (((2 * ks + bhi) ^ swb1) << 4));
        if (DOP) { mma16816(accP[2], aR[1][ks], b0, b1);
                   mma16816(accP[3], aR[1][ks], b2, b3); }
        if (DOC) { mma16816(accC[2], aR[0][ks], b0, b1);
                   mma16816(accC[3], aR[0][ks], b2, b3); }
    }
}

__global__ void __launch_bounds__(NT, 1)
corr_hmma_kernel(float* __restrict__ outg)
{
    extern __shared__ char smc[];
    const uint32_t sb = smem_u32(smc);
    const int tid = threadIdx.x, warp = tid >> 5, lane = tid & 31;
    const int m = warp >> 1;
    const int nh = warp & 1;
    const int jb = blockIdx.x, oh = blockIdx.y, b = blockIdx.z;
    const int j0 = jb * 14;
    const int cnt = (jb == 2) ? 13 : 14;   // rows used: R0 .. R0+cnt
    const int R0 = 2 * oh + j0 - MD;

    // ---- prolog fills: A slabs + B rows R0, R0+1 ----
    const __half* x1b = x1t_g + ((size_t)(b * HH + 2 * oh)) * WW * CHAN;
    fill_slab(sb + SA0, x1b, true, tid);
    fill_slab(sb + SA1, x1b + WW * CHAN, true, tid);
    const __half* x2bb = x2t_g + (size_t)b * HH * WW * CHAN;
#pragma unroll
    for (int k = 0; k < 2; ++k) {
        int row = R0 + k;
        bool v = (unsigned)row < HH;
        fill_slab(sb + SB + k * SLAB, x2bb + (size_t)(v ? row : 0) * WW * CHAN, v, tid);
    }
    asm volatile("cp.async.commit_group;" ::: "memory");

    // ---- ldmatrix addressing ----
    const int cs = min(max(16 * m - 24, 0), 32);
    const int ra = m * 16 + (lane & 15);
    const uint32_t aoff = (uint32_t)(ra * 256);
    const int swa = ra & 7;
    const int ahi = lane >> 4;
    int rb0 = cs + (nh * 4 + 0 + (lane >> 4)) * 8 + (lane & 7);
    int rb1 = cs + (nh * 4 + 2 + (lane >> 4)) * 8 + (lane & 7);
    const uint32_t boff0 = (uint32_t)(rb0 * 256);
    const uint32_t boff1 = (uint32_t)(rb1 * 256);
    const int swb0 = rb0 & 7, swb1 = rb1 & 7;
    const int bhi = (lane >> 3) & 1;

    // ---- epilogue closed-form precompute ----
    // ow = tid%48 (s-invariant), i = tid/48 + 8s
    const int owg = tid % 48;
    const int i0g = tid / 48;
    const int m2  = owg >> 3;
    const int cs2 = min(max(16 * m2 - 24, 0), 32);
    const int r0g = (2 * owg) & 15;
    const int c2b = 2 * owg + i0g - MD;
    const int cmOffW = m2 * (CBPL / 4) + r0g * CBST - cs2;   // word offset in buffer
    const size_t ob = ((size_t)b * (KD * KD) + (size_t)i0g * KD) * (OHH * OWW)
                      + (size_t)oh * OWW + owg;

    // zero pad columns 64,65 of both C buffers (never written by spill)
    {
        int plane = tid >> 5, rem = tid & 31;           // 12 planes x 32 entries
        reinterpret_cast<float*>(smc + SCB + plane * CBPL)
            [(rem >> 1) * CBST + 64 + (rem & 1)] = 0.f;
    }

    // ---- hoist A fragments (once per CTA) ----
    asm volatile("cp.async.wait_group 0;" ::: "memory");
    __syncthreads();
    uint32_t aR[2][8][4];
#pragma unroll
    for (int h = 0; h < 2; ++h) {
        const uint32_t ab = sb + (h ? SA1 : SA0) + aoff;
#pragma unroll
        for (int ks = 0; ks < 8; ++ks)
            ldsm4(aR[h][ks][0], aR[h][ks][1], aR[h][ks][2], aR[h][ks][3],
                  ab + (((2 * ks + ahi) ^ swa) << 4));
    }

    const int spOffW = m * (CBPL / 4);                   // spill plane (word offset)
    const int gr = lane >> 2, ccl = 2 * (lane & 3);

    float accP[4][4], accC[4][4];
#pragma unroll
    for (int t = 0; t < 4; ++t)
#pragma unroll
        for (int q = 0; q < 4; ++q) { accP[t][q] = 0.f; accC[t][q] = 0.f; }

    // gather lambda: read C buffer buf (0/1), emit j = jg
    auto do_gather = [&](int jg, int buf) {
        const float* CB = reinterpret_cast<const float*>(smc + SCB + buf * CBUF);
        const float* CmT = CB + cmOffW;
        const float* zp  = CB + 64;                      // zeroed pad word
        float* op = outg + ob + (size_t)jg * (OHH * OWW);
#pragma unroll
        for (int s = 0; s < 6; ++s) {
            if (s == 5 && tid >= 48) break;
            int c2 = c2b + 8 * s;
            const float* p0 = ((unsigned)c2 < 96u) ? (CmT + c2) : zp;
            const float* p1 = ((unsigned)(c2 + 1) < 96u) ? (CmT + c2 + CBST + 1) : zp;
            op[(size_t)s * (8 * KD * OHH * OWW)] = (*p0 + *p1) * (1.0f / 512.0f);
        }
    };

    // single-barrier pipelined loop
    for (int l = 0; l <= cnt; ++l) {
        asm volatile("cp.async.wait_group 1;" ::: "memory");
        __syncthreads();
        // prefetch row R0+l+2 into slot (l+2)%3
        if (l + 2 <= cnt) {
            int row = R0 + l + 2;
            bool v = (unsigned)row < HH;
            fill_slab(sb + SB + ((l + 2) % 3) * SLAB,
                      x2bb + (size_t)(v ? row : 0) * WW * CHAN, v, tid);
        }
        asm volatile("cp.async.commit_group;" ::: "memory");

        // gather j = l-2 from buffer (l+1)&1 (spilled at iter l-1)
        if (l >= 2) do_gather(j0 + l - 2, (l + 1) & 1);

        const uint32_t bb = sb + SB + (uint32_t)((l % 3) * SLAB);
        if (l == 0)
            mma_row<false, true >(bb, boff0, boff1, swb0, swb1, bhi, aR, accP, accC);
        else if (l == cnt)
            mma_row<true , false>(bb, boff0, boff1, swb0, swb1, bhi, aR, accP, accC);
        else
            mma_row<true , true >(bb, boff0, boff1, swb0, swb1, bhi, aR, accP, accC);

        // spill accP = GEMM(j0+l-1) into buffer l&1
        if (l >= 1) {
            float* Cbm = reinterpret_cast<float*>(smc + SCB + (l & 1) * CBUF) + spOffW;
#pragma unroll
            for (int t = 0; t < 4; ++t) {
                int n = nh * 4 + t;
                *reinterpret_cast<float2*>(Cbm + gr * CBST + n * 8 + ccl) =
                    make_float2(accP[t][0], accP[t][1]);
                *reinterpret_cast<float2*>(Cbm + (gr + 8) * CBST + n * 8 + ccl) =
                    make_float2(accP[t][2], accP[t][3]);
            }
        }
#pragma unroll
        for (int t = 0; t < 4; ++t)
#pragma unroll
            for (int q = 0; q < 4; ++q) { accP[t][q] = accC[t][q]; accC[t][q] = 0.f; }
    }
    // tail: gather j = cnt-1 from buffer cnt&1
    __syncthreads();
    do_gather(j0 + cnt - 1, cnt & 1);
}

extern "C" void kernel_launch(void* const* d_in, const int* in_sizes, int n_in,
                              void* d_out, int out_size)
{
    (void)in_sizes; (void)n_in; (void)out_size;
    const float* x1 = (const float*)d_in[0];
    const float* x2 = (const float*)d_in[1];
    float* out = (float*)d_out;

    static bool attr_set = false;
    if (!attr_set) {
        cudaFuncSetAttribute(corr_hmma_kernel, cudaFuncAttributeMaxDynamicSharedMemorySize,
                             SMEM_MAIN);
        attr_set = true;
    }
    cvt_kernel<<<dim3(HH, BATCH, 2), 256>>>(x1, x2);
    corr_hmma_kernel<<<dim3(3, OHH, BATCH), NT, SMEM_MAIN>>>(out);
}

// round 10
// speedup vs baseline: 5.8892x; 1.0781x over previous
#include <cuda_runtime.h>
#include <cuda_fp16.h>
#include <cstdint>
#include <cstddef>

#define BATCH 4
#define CHAN  128
#define HH    96
#define WW    96
#define MD    20
#define KD    41
#define OHH   48
#define OWW   48

// fp16 channel-last staging: x[b][h][w][ch]
__device__ __half x1t_g[BATCH * HH * WW * CHAN];
__device__ __half x2t_g[BATCH * HH * WW * CHAN];

// ---------- prepass: fp32 [b][ch][h][w] -> fp16 [b][h][w][ch] ----------
__global__ void __launch_bounds__(256, 4)
cvt_kernel(const float* __restrict__ x1, const float* __restrict__ x2)
{
    __shared__ __half2 hsm[WW * 65];
    const int h = blockIdx.x, b = blockIdx.y;
    const float* src = (blockIdx.z == 0) ? x1 : x2;
    __half* dst = (blockIdx.z == 0) ? x1t_g : x2t_g;
    const float* sp = src + ((size_t)b * CHAN) * (HH * WW) + (size_t)h * WW;
    // float2 loads: idx over (cp, wpair); 48 wpairs per row
    for (int idx = threadIdx.x; idx < (CHAN / 2) * (WW / 2); idx += 256) {
        int cp = idx / (WW / 2), wp = idx - cp * (WW / 2);
        float2 r0 = *reinterpret_cast<const float2*>(sp + (size_t)(2 * cp) * (HH * WW) + 2 * wp);
        float2 r1 = *reinterpret_cast<const float2*>(sp + (size_t)(2 * cp + 1) * (HH * WW) + 2 * wp);
        hsm[(2 * wp) * 65 + cp]     = __floats2half2_rn(r0.x, r1.x);
        hsm[(2 * wp + 1) * 65 + cp] = __floats2half2_rn(r0.y, r1.y);
    }
    __syncthreads();
    __half2* dp = reinterpret_cast<__half2*>(dst + ((size_t)(b * HH + h)) * WW * CHAN);
    for (int idx = threadIdx.x; idx < WW * (CHAN / 2); idx += 256) {
        int w = idx >> 6, cp = idx & 63;
        dp[w * (CHAN / 2) + cp] = hsm[w * 65 + cp];
    }
}

// ---------- main kernel ----------
#define NT     384
#define SLAB   24576                     // 96 rows x 256B
#define SA0    0
#define SA1    SLAB
#define SB     (2 * SLAB)                // 3-slot B ring
#define SCB    (5 * SLAB)
#define CBST   68                        // permuted Cbuf row stride (words)
#define CBPL   (16 * CBST * 4)           // 4352 B per plane
#define CBUF   (6 * CBPL)                // 26112 B per C buffer
#define SMEM_MAIN (SCB + 2 * CBUF)       // 175104 B

__device__ __forceinline__ uint32_t smem_u32(const void* p) {
    uint32_t a;
    asm("{ .reg .u64 t; cvta.to.shared.u64 t, %1; cvt.u32.u64 %0, t; }" : "=r"(a) : "l"(p));
    return a;
}
__device__ __forceinline__ void cpa16(uint32_t dst, const void* src, uint32_t sz) {
    asm volatile("cp.async.ca.shared.global [%0], [%1], 16, %2;"
                 :: "r"(dst), "l"(src), "r"(sz) : "memory");
}
__device__ __forceinline__ void fill_slab(uint32_t dstb, const __half* src,
                                          bool valid, int tid)
{
#pragma unroll
    for (int it = 0; it < 4; ++it) {
        int q = tid + it * NT;
        int n = q >> 4, c = q & 15;
        uint32_t dst = dstb + n * 256 + ((c ^ (n & 7)) << 4);
        cpa16(dst, src + n * CHAN + c * 8, valid ? 16u : 0u);
    }
}
__device__ __forceinline__ void ldsm4(uint32_t& r0, uint32_t& r1, uint32_t& r2,
                                      uint32_t& r3, uint32_t a) {
    asm volatile("ldmatrix.sync.aligned.m8n8.x4.shared.b16 {%0,%1,%2,%3}, [%4];"
                 : "=r"(r0), "=r"(r1), "=r"(r2), "=r"(r3) : "r"(a));
}
__device__ __forceinline__ void mma16816(float* c, const uint32_t* a,
                                         uint32_t b0, uint32_t b1) {
    asm volatile("mma.sync.aligned.m16n8k16.row.col.f32.f16.f16.f32 "
                 "{%0,%1,%2,%3},{%4,%5,%6,%7},{%8,%9},{%0,%1,%2,%3};"
                 : "+f"(c[0]), "+f"(c[1]), "+f"(c[2]), "+f"(c[3])
                 : "r"(a[0]), "r"(a[1]), "r"(a[2]), "r"(a[3]), "r"(b0), "r"(b1));
}

template <bool DOP, bool DOC>
__device__ __forceinline__ void mma_row(uint32_t bb, uint32_t boff0, uint32_t boff1,
                                        int swb0, int swb1, int bhi,
                                        const uint32_t aR[2][8][4],
                                        float accP[4][4], float accC[4][4])
{
#pragma unroll
    for (int ks = 0; ks < 8; ++ks) {
        uint32_t b0, b1, b2, b3, c0, c1, c2, c3;
        // issue both LDSMs first, then all 16 MMAs (hide LDSM latency)
        ldsm4(b0, b1, b2, b3, bb + boff0 + (((2 * ks + bhi) ^ swb0) << 4));
        ldsm4(c0, c1, c2, c3, bb + boff1 + (((2 * ks + bhi) ^ swb1) << 4));
        if (DOP) { mma16816(accP[0], aR[1][ks], b0, b1);
                   mma16816(accP[1], aR[1][ks], b2, b3);
                   mma16816(accP[2], aR[1][ks], c0, c1);
                   mma16816(accP[3], aR[1][ks], c2, c3); }
        if (DOC) { mma16816(accC[0], aR[0][ks], b0, b1);
                   mma16816(accC[1], aR[0][ks], b2, b3);
                   mma16816(accC[2], aR[0][ks], c0, c1);
                   mma16816(accC[3], aR[0][ks], c2, c3); }
    }
}

__global__ void __launch_bounds__(NT, 1)
corr_hmma_kernel(float* __restrict__ outg)
{
    extern __shared__ char smc[];
    const uint32_t sb = smem_u32(smc);
    const int tid = threadIdx.x, warp = tid >> 5, lane = tid & 31;
    const int m = warp >> 1;
    const int nh = warp & 1;
    const int jb = blockIdx.x, oh = blockIdx.y, b = blockIdx.z;
    const int j0 = jb * 14;
    const int cnt = (jb == 2) ? 13 : 14;   // rows used: R0 .. R0+cnt
    const int R0 = 2 * oh + j0 - MD;

    // ---- prolog fills: A slabs + B rows R0, R0+1 ----
    const __half* x1b = x1t_g + ((size_t)(b * HH + 2 * oh)) * WW * CHAN;
    fill_slab(sb + SA0, x1b, true, tid);
    fill_slab(sb + SA1, x1b + WW * CHAN, true, tid);
    const __half* x2bb = x2t_g + (size_t)b * HH * WW * CHAN;
#pragma unroll
    for (int k = 0; k < 2; ++k) {
        int row = R0 + k;
        bool v = (unsigned)row < HH;
        fill_slab(sb + SB + k * SLAB, x2bb + (size_t)(v ? row : 0) * WW * CHAN, v, tid);
    }
    asm volatile("cp.async.commit_group;" ::: "memory");

    // ---- ldmatrix addressing ----
    const int cs = min(max(16 * m - 24, 0), 32);
    const int ra = m * 16 + (lane & 15);
    const uint32_t aoff = (uint32_t)(ra * 256);
    const int swa = ra & 7;
    const int ahi = lane >> 4;
    int rb0 = cs + (nh * 4 + 0 + (lane >> 4)) * 8 + (lane & 7);
    int rb1 = cs + (nh * 4 + 2 + (lane >> 4)) * 8 + (lane & 7);
    const uint32_t boff0 = (uint32_t)(rb0 * 256);
    const uint32_t boff1 = (uint32_t)(rb1 * 256);
    const int swb0 = rb0 & 7, swb1 = rb1 & 7;
    const int bhi = (lane >> 3) & 1;

    // ---- epilogue closed-form precompute (permuted Cbuf) ----
    // ow = tid%48, i = tid/48 + 8s; c2 = 2ow + i - 20 (+8s, parity fixed)
    const int owg = tid % 48;
    const int i0g = tid / 48;
    const int m2  = owg >> 3;
    const int cs2 = min(max(16 * m2 - 24, 0), 32);
    const int r0g = (2 * owg) & 15;
    const int c2b = 2 * owg + i0g - MD;            // global col of p0 at s=0
    const int par = c2b & 1;
    // word offsets within a C buffer for p0 (row r0g) and p1 (row r0g+1):
    // local col cl = c2 - cs2; pcol(cl) = (cl>>1) + (cl&1)*33
    const int base0 = m2 * (CBPL / 4) + r0g * CBST;
    const int base1 = base0 + CBST;
    const size_t ob = ((size_t)b * (KD * KD) + (size_t)i0g * KD) * (OHH * OWW)
                      + (size_t)oh * OWW + owg;

    // zero pad slot (col 32 of every plane-row, both buffers) — never written
    {
        int plane = tid >> 5, rem = tid & 31;      // 12 planes x 32 entries
        float* P = reinterpret_cast<float*>(smc + SCB + plane * CBPL);
        if (rem < 16) P[rem * CBST + 32] = 0.f;
        else P[(rem - 16) * CBST + 66] = 0.f;      // spare, harmless
    }

    // ---- hoist A fragments (once per CTA) ----
    asm volatile("cp.async.wait_group 0;" ::: "memory");
    __syncthreads();
    uint32_t aR[2][8][4];
#pragma unroll
    for (int h = 0; h < 2; ++h) {
        const uint32_t ab = sb + (h ? SA1 : SA0) + aoff;
#pragma unroll
        for (int ks = 0; ks < 8; ++ks)
            ldsm4(aR[h][ks][0], aR[h][ks][1], aR[h][ks][2], aR[h][ks][3],
                  ab + (((2 * ks + ahi) ^ swa) << 4));
    }

    const int spOffW = m * (CBPL / 4);
    const int gr = lane >> 2, kk = lane & 3;

    float accP[4][4], accC[4][4];
#pragma unroll
    for (int t = 0; t < 4; ++t)
#pragma unroll
        for (int q = 0; q < 4; ++q) { accP[t][q] = 0.f; accC[t][q] = 0.f; }

    // gather: read permuted C buffer buf, emit j = jg
    auto do_gather = [&](int jg, int buf) {
        const float* CB = reinterpret_cast<const float*>(smc + SCB + buf * CBUF);
        const float* zp = CB + 32;                 // zeroed pad slot
        float* op = outg + ob + (size_t)jg * (OHH * OWW);
#pragma unroll
        for (int s = 0; s < 6; ++s) {
            if (s == 5 && tid >= 48) break;
            int c2 = c2b + 8 * s;                  // p0 col (parity par)
            int cl0 = c2 - cs2;                    // 0..63 when valid
            int cl1 = cl0 + 1;
            const float* p0 = ((unsigned)c2 < 96u)
                ? (CB + base0 + (cl0 >> 1) + par * 33) : zp;
            const float* p1 = ((unsigned)(c2 + 1) < 96u)
                ? (CB + base1 + (cl1 >> 1) + (1 - par) * 33) : zp;
            op[(size_t)s * (8 * KD * OHH * OWW)] = (*p0 + *p1) * (1.0f / 512.0f);
        }
    };

    for (int l = 0; l <= cnt; ++l) {
        asm volatile("cp.async.wait_group 1;" ::: "memory");
        __syncthreads();
        if (l + 2 <= cnt) {
            int row = R0 + l + 2;
            bool v = (unsigned)row < HH;
            fill_slab(sb + SB + ((l + 2) % 3) * SLAB,
                      x2bb + (size_t)(v ? row : 0) * WW * CHAN, v, tid);
        }
        asm volatile("cp.async.commit_group;" ::: "memory");

        if (l >= 2) do_gather(j0 + l - 2, (l + 1) & 1);

        const uint32_t bb = sb + SB + (uint32_t)((l % 3) * SLAB);
        if (l == 0)
            mma_row<false, true >(bb, boff0, boff1, swb0, swb1, bhi, aR, accP, accC);
        else if (l == cnt)
            mma_row<true , false>(bb, boff0, boff1, swb0, swb1, bhi, aR, accP, accC);
        else
            mma_row<true , true >(bb, boff0, boff1, swb0, swb1, bhi, aR, accP, accC);

        // spill accP = GEMM(j0+l-1) into buffer l&1 (permuted layout)
        if (l >= 1) {
            float* Cbm = reinterpret_cast<float*>(smc + SCB + (l & 1) * CBUF) + spOffW;
#pragma unroll
            for (int t = 0; t < 4; ++t) {
                int n = nh * 4 + t;
                int slot = n * 4 + kk;             // even col c -> slot c/2
                Cbm[gr * CBST + slot]            = accP[t][0];
                Cbm[gr * CBST + slot + 33]       = accP[t][1];
                Cbm[(gr + 8) * CBST + slot]      = accP[t][2];
                Cbm[(gr + 8) * CBST + slot + 33] = accP[t][3];
            }
        }
#pragma unroll
        for (int t = 0; t < 4; ++t)
#pragma unroll
            for (int q = 0; q < 4; ++q) { accP[t][q] = accC[t][q]; accC[t][q] = 0.f; }
    }
    __syncthreads();
    do_gather(j0 + cnt - 1, cnt & 1);
}

extern "C" void kernel_launch(void* const* d_in, const int* in_sizes, int n_in,
                              void* d_out, int out_size)
{
    (void)in_sizes; (void)n_in; (void)out_size;
    const float* x1 = (const float*)d_in[0];
    const float* x2 = (const float*)d_in[1];
    float* out = (float*)d_out;

    static bool attr_set = false;
    if (!attr_set) {
        cudaFuncSetAttribute(corr_hmma_kernel, cudaFuncAttributeMaxDynamicSharedMemorySize,
                             SMEM_MAIN);
        attr_set = true;
    }
    cvt_kernel<<<dim3(HH, BATCH, 2), 256>>>(x1, x2);
    corr_hmma_kernel<<<dim3(3, OHH, BATCH), NT, SMEM_MAIN>>>(out);
}

// round 11
// speedup vs baseline: 5.9677x; 1.0133x over previous
#include <cuda_runtime.h>
#include <cuda_fp16.h>
#include <cstdint>
#include <cstddef>

#define BATCH 4
#define CHAN  128
#define HH    96
#define WW    96
#define MD    20
#define KD    41
#define OHH   48
#define OWW   48

// fp16 channel-last staging: x[b][h][w][ch]
__device__ __half x1t_g[BATCH * HH * WW * CHAN];
__device__ __half x2t_g[BATCH * HH * WW * CHAN];

// ---------- prepass: fp32 [b][ch][h][w] -> fp16 [b][h][w][ch] ----------
// LDG.128; STS mapping (4wq+k)*65+cp with cp=tid>>3, wq8=tid&7 -> conflict-free
__global__ void __launch_bounds__(256, 4)
cvt_kernel(const float* __restrict__ x1, const float* __restrict__ x2)
{
    __shared__ __half2 hsm[WW * 65];
    const int h = blockIdx.x, b = blockIdx.y;
    const float* src = (blockIdx.z == 0) ? x1 : x2;
    __half* dst = (blockIdx.z == 0) ? x1t_g : x2t_g;
    const float* sp = src + ((size_t)b * CHAN) * (HH * WW) + (size_t)h * WW;

    const int cp0 = threadIdx.x >> 3;          // 0..31
    const int wq8 = threadIdx.x & 7;           // 0..7
#pragma unroll
    for (int cph = 0; cph < 2; ++cph) {
        int cp = cp0 + 32 * cph;
        const float* r0 = sp + (size_t)(2 * cp) * (HH * WW);
        const float* r1 = r0 + HH * WW;
#pragma unroll
        for (int it = 0; it < 3; ++it) {
            int wq = wq8 + 8 * it;
            float4 a = *reinterpret_cast<const float4*>(r0 + 4 * wq);
            float4 c = *reinterpret_cast<const float4*>(r1 + 4 * wq);
            hsm[(4 * wq + 0) * 65 + cp] = __floats2half2_rn(a.x, c.x);
            hsm[(4 * wq + 1) * 65 + cp] = __floats2half2_rn(a.y, c.y);
            hsm[(4 * wq + 2) * 65 + cp] = __floats2half2_rn(a.z, c.z);
            hsm[(4 * wq + 3) * 65 + cp] = __floats2half2_rn(a.w, c.w);
        }
    }
    __syncthreads();
    __half2* dp = reinterpret_cast<__half2*>(dst + ((size_t)(b * HH + h)) * WW * CHAN);
    for (int idx = threadIdx.x; idx < WW * (CHAN / 2); idx += 256) {
        int w = idx >> 6, cp = idx & 63;
        dp[w * (CHAN / 2) + cp] = hsm[w * 65 + cp];
    }
}

// ---------- main kernel ----------
#define NT     384
#define SLAB   24576                     // 96 rows x 256B
#define SA0    0
#define SA1    SLAB
#define SB     (2 * SLAB)                // 3-slot B ring
#define SCB    (5 * SLAB)
#define CBST   68                        // permuted Cbuf row stride (words)
#define CBPL   (16 * CBST * 4)           // 4352 B per plane
#define CBUF   (6 * CBPL)                // 26112 B per C buffer
#define SMEM_MAIN (SCB + 2 * CBUF)       // 175104 B

__device__ __forceinline__ uint32_t smem_u32(const void* p) {
    uint32_t a;
    asm("{ .reg .u64 t; cvta.to.shared.u64 t, %1; cvt.u32.u64 %0, t; }" : "=r"(a) : "l"(p));
    return a;
}
__device__ __forceinline__ void cpa16(uint32_t dst, const void* src, uint32_t sz) {
    asm volatile("cp.async.ca.shared.global [%0], [%1], 16, %2;"
                 :: "r"(dst), "l"(src), "r"(sz) : "memory");
}
__device__ __forceinline__ void fill_slab(uint32_t dstb, const __half* src,
                                          bool valid, int tid)
{
#pragma unroll
    for (int it = 0; it < 4; ++it) {
        int q = tid + it * NT;
        int n = q >> 4, c = q & 15;
        uint32_t dst = dstb + n * 256 + ((c ^ (n & 7)) << 4);
        cpa16(dst, src + n * CHAN + c * 8, valid ? 16u : 0u);
    }
}
__device__ __forceinline__ void ldsm4(uint32_t& r0, uint32_t& r1, uint32_t& r2,
                                      uint32_t& r3, uint32_t a) {
    asm volatile("ldmatrix.sync.aligned.m8n8.x4.shared.b16 {%0,%1,%2,%3}, [%4];"
                 : "=r"(r0), "=r"(r1), "=r"(r2), "=r"(r3) : "r"(a));
}
__device__ __forceinline__ void mma16816(float* c, const uint32_t* a,
                                         uint32_t b0, uint32_t b1) {
    asm volatile("mma.sync.aligned.m16n8k16.row.col.f32.f16.f16.f32 "
                 "{%0,%1,%2,%3},{%4,%5,%6,%7},{%8,%9},{%0,%1,%2,%3};"
                 : "+f"(c[0]), "+f"(c[1]), "+f"(c[2]), "+f"(c[3])
                 : "r"(a[0]), "r"(a[1]), "r"(a[2]), "r"(a[3]), "r"(b0), "r"(b1));
}

template <bool DOP, bool DOC>
__device__ __forceinline__ void mma_row(uint32_t bb, uint32_t boff0, uint32_t boff1,
                                        int swb0, int swb1, int bhi,
                                        const uint32_t aR[2][8][4],
                                        float accP[4][4], float accC[4][4])
{
#pragma unroll
    for (int ks = 0; ks < 8; ++ks) {
        uint32_t b0, b1, b2, b3, c0, c1, c2, c3;
        ldsm4(b0, b1, b2, b3, bb + boff0 + (((2 * ks + bhi) ^ swb0) << 4));
        ldsm4(c0, c1, c2, c3, bb + boff1 + (((2 * ks + bhi) ^ swb1) << 4));
        if (DOP) { mma16816(accP[0], aR[1][ks], b0, b1);
                   mma16816(accP[1], aR[1][ks], b2, b3);
                   mma16816(accP[2], aR[1][ks], c0, c1);
                   mma16816(accP[3], aR[1][ks], c2, c3); }
        if (DOC) { mma16816(accC[0], aR[0][ks], b0, b1);
                   mma16816(accC[1], aR[0][ks], b2, b3);
                   mma16816(accC[2], aR[0][ks], c0, c1);
                   mma16816(accC[3], aR[0][ks], c2, c3); }
    }
}

// corner warps: single band tile; lowsel picks (b0,b1) vs (b2,b3); acc into slot 0
template <bool DOP, bool DOC>
__device__ __forceinline__ void corner_row(uint32_t bb, uint32_t boff, int swb, int bhi,
                                           bool lowsel, const uint32_t aR[2][8][4],
                                           float accP[4][4], float accC[4][4])
{
#pragma unroll
    for (int ks = 0; ks < 8; ++ks) {
        uint32_t b0, b1, b2, b3;
        ldsm4(b0, b1, b2, b3, bb + boff + (((2 * ks + bhi) ^ swb) << 4));
        uint32_t u0 = lowsel ? b0 : b2;
        uint32_t u1 = lowsel ? b1 : b3;
        if (DOP) mma16816(accP[0], aR[1][ks], u0, u1);
        if (DOC) mma16816(accC[0], aR[0][ks], u0, u1);
    }
}

__global__ void __launch_bounds__(NT, 1)
corr_hmma_kernel(float* __restrict__ outg)
{
    extern __shared__ char smc[];
    const uint32_t sb = smem_u32(smc);
    const int tid = threadIdx.x, warp = tid >> 5, lane = tid & 31;
    const int m = warp >> 1;
    const int nh = warp & 1;
    const int jb = blockIdx.x, oh = blockIdx.y, b = blockIdx.z;
    const int j0 = jb * 14;
    const int cnt = (jb == 2) ? 13 : 14;   // rows used: R0 .. R0+cnt
    const int R0 = 2 * oh + j0 - MD;

    // ---- prolog fills: A slabs + B rows R0, R0+1 ----
    const __half* x1b = x1t_g + ((size_t)(b * HH + 2 * oh)) * WW * CHAN;
    fill_slab(sb + SA0, x1b, true, tid);
    fill_slab(sb + SA1, x1b + WW * CHAN, true, tid);
    const __half* x2bb = x2t_g + (size_t)b * HH * WW * CHAN;
#pragma unroll
    for (int k = 0; k < 2; ++k) {
        int row = R0 + k;
        bool v = (unsigned)row < HH;
        fill_slab(sb + SB + k * SLAB, x2bb + (size_t)(v ? row : 0) * WW * CHAN, v, tid);
    }
    asm volatile("cp.async.commit_group;" ::: "memory");

    // ---- ldmatrix addressing ----
    const int cs = min(max(16 * m - 24, 0), 32);
    const int ra = m * 16 + (lane & 15);
    const uint32_t aoff = (uint32_t)(ra * 256);
    const int swa = ra & 7;
    const int ahi = lane >> 4;
    int rb0 = cs + (nh * 4 + 0 + (lane >> 4)) * 8 + (lane & 7);
    int rb1 = cs + (nh * 4 + 2 + (lane >> 4)) * 8 + (lane & 7);
    uint32_t boff0 = (uint32_t)(rb0 * 256);
    uint32_t boff1 = (uint32_t)(rb1 * 256);
    int swb0 = rb0 & 7, swb1 = rb1 & 7;
    const int bhi = (lane >> 3) & 1;

    // corner warps: warp 1 (m=0,nh=1) needs only tile n=4 (cols 32-39, band<=35);
    // warp 10 (m=5,nh=0) needs only tile n=3 (cols 56-63, band>=60).
    const bool corner = (warp == 1) || (warp == 10);
    const bool lowsel = (warp == 1);
    const int  cn     = lowsel ? 4 : 3;          // spill slot n for corner warps
    if (warp == 10) { boff0 = boff1; swb0 = swb1; }  // corner uses boff0/swb0

    // ---- epilogue closed-form precompute (permuted Cbuf) ----
    const int owg = tid % 48;
    const int i0g = tid / 48;
    const int m2  = owg >> 3;
    const int cs2 = min(max(16 * m2 - 24, 0), 32);
    const int r0g = (2 * owg) & 15;
    const int c2b = 2 * owg + i0g - MD;
    const int par = c2b & 1;
    const int base0 = m2 * (CBPL / 4) + r0g * CBST;
    const int base1 = base0 + CBST;
    const size_t ob = ((size_t)b * (KD * KD) + (size_t)i0g * KD) * (OHH * OWW)
                      + (size_t)oh * OWW + owg;

    // zero pad slot (col 32 of every plane-row, both buffers)
    {
        int plane = tid >> 5, rem = tid & 31;
        float* P = reinterpret_cast<float*>(smc + SCB + plane * CBPL);
        if (rem < 16) P[rem * CBST + 32] = 0.f;
        else P[(rem - 16) * CBST + 66] = 0.f;
    }

    // ---- hoist A fragments (once per CTA) ----
    asm volatile("cp.async.wait_group 0;" ::: "memory");
    __syncthreads();
    uint32_t aR[2][8][4];
#pragma unroll
    for (int h = 0; h < 2; ++h) {
        const uint32_t ab = sb + (h ? SA1 : SA0) + aoff;
#pragma unroll
        for (int ks = 0; ks < 8; ++ks)
            ldsm4(aR[h][ks][0], aR[h][ks][1], aR[h][ks][2], aR[h][ks][3],
                  ab + (((2 * ks + ahi) ^ swa) << 4));
    }

    const int spOffW = m * (CBPL / 4);
    const int gr = lane >> 2, kk = lane & 3;

    float accP[4][4], accC[4][4];
#pragma unroll
    for (int t = 0; t < 4; ++t)
#pragma unroll
        for (int q = 0; q < 4; ++q) { accP[t][q] = 0.f; accC[t][q] = 0.f; }

    auto do_gather = [&](int jg, int buf) {
        const float* CB = reinterpret_cast<const float*>(smc + SCB + buf * CBUF);
        const float* zp = CB + 32;
        float* op = outg + ob + (size_t)jg * (OHH * OWW);
#pragma unroll
        for (int s = 0; s < 6; ++s) {
            if (s == 5 && tid >= 48) break;
            int c2 = c2b + 8 * s;
            int cl0 = c2 - cs2;
            int cl1 = cl0 + 1;
            const float* p0 = ((unsigned)c2 < 96u)
                ? (CB + base0 + (cl0 >> 1) + par * 33) : zp;
            const float* p1 = ((unsigned)(c2 + 1) < 96u)
                ? (CB + base1 + (cl1 >> 1) + (1 - par) * 33) : zp;
            op[(size_t)s * (8 * KD * OHH * OWW)] = (*p0 + *p1) * (1.0f / 512.0f);
        }
    };

    for (int l = 0; l <= cnt; ++l) {
        asm volatile("cp.async.wait_group 1;" ::: "memory");
        __syncthreads();
        if (l + 2 <= cnt) {
            int row = R0 + l + 2;
            bool v = (unsigned)row < HH;
            fill_slab(sb + SB + ((l + 2) % 3) * SLAB,
                      x2bb + (size_t)(v ? row : 0) * WW * CHAN, v, tid);
        }
        asm volatile("cp.async.commit_group;" ::: "memory");

        if (l >= 2) do_gather(j0 + l - 2, (l + 1) & 1);

        const uint32_t bb = sb + SB + (uint32_t)((l % 3) * SLAB);
        if (!corner) {
            if (l == 0)
                mma_row<false, true >(bb, boff0, boff1, swb0, swb1, bhi, aR, accP, accC);
            else if (l == cnt)
                mma_row<true , false>(bb, boff0, boff1, swb0, swb1, bhi, aR, accP, accC);
            else
                mma_row<true , true >(bb, boff0, boff1, swb0, swb1, bhi, aR, accP, accC);
        } else {
            if (l == 0)
                corner_row<false, true >(bb, boff0, swb0, bhi, lowsel, aR, accP, accC);
            else if (l == cnt)
                corner_row<true , false>(bb, boff0, swb0, bhi, lowsel, aR, accP, accC);
            else
                corner_row<true , true >(bb, boff0, swb0, bhi, lowsel, aR, accP, accC);
        }

        // spill accP = GEMM(j0+l-1) into buffer l&1 (permuted layout)
        if (l >= 1) {
            float* Cbm = reinterpret_cast<float*>(smc + SCB + (l & 1) * CBUF) + spOffW;
            if (!corner) {
#pragma unroll
                for (int t = 0; t < 4; ++t) {
                    int n = nh * 4 + t;
                    int slot = n * 4 + kk;
                    Cbm[gr * CBST + slot]            = accP[t][0];
                    Cbm[gr * CBST + slot + 33]       = accP[t][1];
                    Cbm[(gr + 8) * CBST + slot]      = accP[t][2];
                    Cbm[(gr + 8) * CBST + slot + 33] = accP[t][3];
                }
            } else {
                int slot = cn * 4 + kk;
                Cbm[gr * CBST + slot]            = accP[0][0];
                Cbm[gr * CBST + slot + 33]       = accP[0][1];
                Cbm[(gr + 8) * CBST + slot]      = accP[0][2];
                Cbm[(gr + 8) * CBST + slot + 33] = accP[0][3];
            }
        }
#pragma unroll
        for (int t = 0; t < 4; ++t)
#pragma unroll
            for (int q = 0; q < 4; ++q) { accP[t][q] = accC[t][q]; accC[t][q] = 0.f; }
    }
    __syncthreads();
    do_gather(j0 + cnt - 1, cnt & 1);
}

extern "C" void kernel_launch(void* const* d_in, const int* in_sizes, int n_in,
                              void* d_out, int out_size)
{
    (void)in_sizes; (void)n_in; (void)out_size;
    const float* x1 = (const float*)d_in[0];
    const float* x2 = (const float*)d_in[1];
    float* out = (float*)d_out;

    static bool attr_set = false;
    if (!attr_set) {
        cudaFuncSetAttribute(corr_hmma_kernel, cudaFuncAttributeMaxDynamicSharedMemorySize,
                             SMEM_MAIN);
        attr_set = true;
    }
    cvt_kernel<<<dim3(HH, BATCH, 2), 256>>>(x1, x2);
    corr_hmma_kernel<<<dim3(3, OHH, BATCH), NT, SMEM_MAIN>>>(out);
}

// round 12
// speedup vs baseline: 6.1274x; 1.0268x over previous
#include <cuda_runtime.h>
#include <cuda_fp16.h>
#include <cstdint>
#include <cstddef>

#define BATCH 4
#define CHAN  128
#define HH    96
#define WW    96
#define MD    20
#define KD    41
#define OHH   48
#define OWW   48

// fp16 channel-last staging: x[b][h][w][ch]
__device__ __half x1t_g[BATCH * HH * WW * CHAN];
__device__ __half x2t_g[BATCH * HH * WW * CHAN];

// ---------- prepass: fp32 [b][ch][h][w] -> fp16 [b][h][w][ch] ----------
// LDG.128; STS mapping (4wq+k)*65+cp with cp=tid>>3, wq8=tid&7 -> conflict-free
__global__ void __launch_bounds__(256, 4)
cvt_kernel(const float* __restrict__ x1, const float* __restrict__ x2)
{
    __shared__ __half2 hsm[WW * 65];
    const int h = blockIdx.x, b = blockIdx.y;
    const float* src = (blockIdx.z == 0) ? x1 : x2;
    __half* dst = (blockIdx.z == 0) ? x1t_g : x2t_g;
    const float* sp = src + ((size_t)b * CHAN) * (HH * WW) + (size_t)h * WW;

    const int cp0 = threadIdx.x >> 3;          // 0..31
    const int wq8 = threadIdx.x & 7;           // 0..7
#pragma unroll
    for (int cph = 0; cph < 2; ++cph) {
        int cp = cp0 + 32 * cph;
        const float* r0 = sp + (size_t)(2 * cp) * (HH * WW);
        const float* r1 = r0 + HH * WW;
#pragma unroll
        for (int it = 0; it < 3; ++it) {
            int wq = wq8 + 8 * it;
            float4 a = *reinterpret_cast<const float4*>(r0 + 4 * wq);
            float4 c = *reinterpret_cast<const float4*>(r1 + 4 * wq);
            hsm[(4 * wq + 0) * 65 + cp] = __floats2half2_rn(a.x, c.x);
            hsm[(4 * wq + 1) * 65 + cp] = __floats2half2_rn(a.y, c.y);
            hsm[(4 * wq + 2) * 65 + cp] = __floats2half2_rn(a.z, c.z);
            hsm[(4 * wq + 3) * 65 + cp] = __floats2half2_rn(a.w, c.w);
        }
    }
    __syncthreads();
    __half2* dp = reinterpret_cast<__half2*>(dst + ((size_t)(b * HH + h)) * WW * CHAN);
    for (int idx = threadIdx.x; idx < WW * (CHAN / 2); idx += 256) {
        int w = idx >> 6, cp = idx & 63;
        dp[w * (CHAN / 2) + cp] = hsm[w * 65 + cp];
    }
}

// ---------- main kernel ----------
#define NT     384
#define SLAB   24576                     // 96 rows x 256B
#define SA0    0
#define SA1    SLAB
#define SB     (2 * SLAB)                // 3-slot B ring
#define SCB    (5 * SLAB)
#define CBST   68                        // permuted Cbuf row stride (words)
#define CBPL   (16 * CBST * 4)           // 4352 B per plane
#define CBUF   (6 * CBPL)                // 26112 B per C buffer
#define SMEM_MAIN (SCB + 2 * CBUF)       // 175104 B

__device__ __forceinline__ uint32_t smem_u32(const void* p) {
    uint32_t a;
    asm("{ .reg .u64 t; cvta.to.shared.u64 t, %1; cvt.u32.u64 %0, t; }" : "=r"(a) : "l"(p));
    return a;
}
__device__ __forceinline__ void cpa16(uint32_t dst, const void* src, uint32_t sz) {
    asm volatile("cp.async.ca.shared.global [%0], [%1], 16, %2;"
                 :: "r"(dst), "l"(src), "r"(sz) : "memory");
}
__device__ __forceinline__ void fill_slab(uint32_t dstb, const __half* src,
                                          bool valid, int tid)
{
#pragma unroll
    for (int it = 0; it < 4; ++it) {
        int q = tid + it * NT;
        int n = q >> 4, c = q & 15;
        uint32_t dst = dstb + n * 256 + ((c ^ (n & 7)) << 4);
        cpa16(dst, src + n * CHAN + c * 8, valid ? 16u : 0u);
    }
}
__device__ __forceinline__ void ldsm4(uint32_t& r0, uint32_t& r1, uint32_t& r2,
                                      uint32_t& r3, uint32_t a) {
    asm volatile("ldmatrix.sync.aligned.m8n8.x4.shared.b16 {%0,%1,%2,%3}, [%4];"
                 : "=r"(r0), "=r"(r1), "=r"(r2), "=r"(r3) : "r"(a));
}
__device__ __forceinline__ void mma16816(float* c, const uint32_t* a,
                                         uint32_t b0, uint32_t b1) {
    asm volatile("mma.sync.aligned.m16n8k16.row.col.f32.f16.f16.f32 "
                 "{%0,%1,%2,%3},{%4,%5,%6,%7},{%8,%9},{%0,%1,%2,%3};"
                 : "+f"(c[0]), "+f"(c[1]), "+f"(c[2]), "+f"(c[3])
                 : "r"(a[0]), "r"(a[1]), "r"(a[2]), "r"(a[3]), "r"(b0), "r"(b1));
}

template <bool DOP, bool DOC>
__device__ __forceinline__ void mma_row(uint32_t bb, uint32_t boff0, uint32_t boff1,
                                        int swb0, int swb1, int bhi,
                                        const uint32_t aR[2][8][4],
                                        float accP[4][4], float accC[4][4])
{
#pragma unroll
    for (int ks = 0; ks < 8; ++ks) {
        uint32_t b0, b1, b2, b3, c0, c1, c2, c3;
        ldsm4(b0, b1, b2, b3, bb + boff0 + (((2 * ks + bhi) ^ swb0) << 4));
        ldsm4(c0, c1, c2, c3, bb + boff1 + (((2 * ks + bhi) ^ swb1) << 4));
        if (DOP) { mma16816(accP[0], aR[1][ks], b0, b1);
                   mma16816(accP[1], aR[1][ks], b2, b3);
                   mma16816(accP[2], aR[1][ks], c0, c1);
                   mma16816(accP[3], aR[1][ks], c2, c3); }
        if (DOC) { mma16816(accC[0], aR[0][ks], b0, b1);
                   mma16816(accC[1], aR[0][ks], b2, b3);
                   mma16816(accC[2], aR[0][ks], c0, c1);
                   mma16816(accC[3], aR[0][ks], c2, c3); }
    }
}

__global__ void __launch_bounds__(NT, 1)
corr_hmma_kernel(float* __restrict__ outg)
{
    extern __shared__ char smc[];
    const uint32_t sb = smem_u32(smc);
    const int tid = threadIdx.x, warp = tid >> 5, lane = tid & 31;
    const int m = warp >> 1;
    const int nh = warp & 1;
    const int jb = blockIdx.x, oh = blockIdx.y, b = blockIdx.z;
    const int j0 = jb * 14;
    const int cnt = (jb == 2) ? 13 : 14;   // rows used: R0 .. R0+cnt
    const int R0 = 2 * oh + j0 - MD;

    // ---- prolog fills: A slabs + B rows R0, R0+1 ----
    const __half* x1b = x1t_g + ((size_t)(b * HH + 2 * oh)) * WW * CHAN;
    fill_slab(sb + SA0, x1b, true, tid);
    fill_slab(sb + SA1, x1b + WW * CHAN, true, tid);
    const __half* x2bb = x2t_g + (size_t)b * HH * WW * CHAN;
#pragma unroll
    for (int k = 0; k < 2; ++k) {
        int row = R0 + k;
        bool v = (unsigned)row < HH;
        fill_slab(sb + SB + k * SLAB, x2bb + (size_t)(v ? row : 0) * WW * CHAN, v, tid);
    }
    asm volatile("cp.async.commit_group;" ::: "memory");

    // ---- ldmatrix addressing ----
    const int cs = min(max(16 * m - 24, 0), 32);
    const int ra = m * 16 + (lane & 15);
    const uint32_t aoff = (uint32_t)(ra * 256);
    const int swa = ra & 7;
    const int ahi = lane >> 4;
    int rb0 = cs + (nh * 4 + 0 + (lane >> 4)) * 8 + (lane & 7);
    int rb1 = cs + (nh * 4 + 2 + (lane >> 4)) * 8 + (lane & 7);
    const uint32_t boff0 = (uint32_t)(rb0 * 256);
    const uint32_t boff1 = (uint32_t)(rb1 * 256);
    const int swb0 = rb0 & 7, swb1 = rb1 & 7;
    const int bhi = (lane >> 3) & 1;

    // ---- epilogue closed-form precompute (permuted Cbuf) ----
    const int owg = tid % 48;
    const int i0g = tid / 48;
    const int m2  = owg >> 3;
    const int cs2 = min(max(16 * m2 - 24, 0), 32);
    const int r0g = (2 * owg) & 15;
    const int c2b = 2 * owg + i0g - MD;
    const int par = c2b & 1;
    const int base0 = m2 * (CBPL / 4) + r0g * CBST;
    const int base1 = base0 + CBST;
    const size_t ob = ((size_t)b * (KD * KD) + (size_t)i0g * KD) * (OHH * OWW)
                      + (size_t)oh * OWW + owg;

    // zero pad slot (col 32 of every plane-row, both buffers)
    {
        int plane = tid >> 5, rem = tid & 31;
        float* P = reinterpret_cast<float*>(smc + SCB + plane * CBPL);
        if (rem < 16) P[rem * CBST + 32] = 0.f;
        else P[(rem - 16) * CBST + 66] = 0.f;
    }

    // ---- hoist A fragments (once per CTA) ----
    asm volatile("cp.async.wait_group 0;" ::: "memory");
    __syncthreads();
    uint32_t aR[2][8][4];
#pragma unroll
    for (int h = 0; h < 2; ++h) {
        const uint32_t ab = sb + (h ? SA1 : SA0) + aoff;
#pragma unroll
        for (int ks = 0; ks < 8; ++ks)
            ldsm4(aR[h][ks][0], aR[h][ks][1], aR[h][ks][2], aR[h][ks][3],
                  ab + (((2 * ks + ahi) ^ swa) << 4));
    }

    const int spOffW = m * (CBPL / 4);
    const int gr = lane >> 2, kk = lane & 3;

    float accP[4][4], accC[4][4];
#pragma unroll
    for (int t = 0; t < 4; ++t)
#pragma unroll
        for (int q = 0; q < 4; ++q) { accP[t][q] = 0.f; accC[t][q] = 0.f; }

    auto do_gather = [&](int jg, int buf) {
        const float* CB = reinterpret_cast<const float*>(smc + SCB + buf * CBUF);
        const float* zp = CB + 32;
        float* op = outg + ob + (size_t)jg * (OHH * OWW);
#pragma unroll
        for (int s = 0; s < 6; ++s) {
            if (s == 5 && tid >= 48) break;
            int c2 = c2b + 8 * s;
            int cl0 = c2 - cs2;
            int cl1 = cl0 + 1;
            const float* p0 = ((unsigned)c2 < 96u)
                ? (CB + base0 + (cl0 >> 1) + par * 33) : zp;
            const float* p1 = ((unsigned)(c2 + 1) < 96u)
                ? (CB + base1 + (cl1 >> 1) + (1 - par) * 33) : zp;
            op[(size_t)s * (8 * KD * OHH * OWW)] = (*p0 + *p1) * (1.0f / 512.0f);
        }
    };

    // loop: iter l consumes B row R0+l once; gather overlapped with B-fill wait
    for (int l = 0; l <= cnt; ++l) {
        __syncthreads();                  // spill(l-1) visible; slot (l+2)%3 free
        // issue prefetch of row R0+l+2 BEFORE waiting (deepens overlap)
        if (l + 2 <= cnt) {
            int row = R0 + l + 2;
            bool v = (unsigned)row < HH;
            fill_slab(sb + SB + ((l + 2) % 3) * SLAB,
                      x2bb + (size_t)(v ? row : 0) * WW * CHAN, v, tid);
        }
        asm volatile("cp.async.commit_group;" ::: "memory");

        // gather j=l-2 (independent of incoming B row) inside the fill shadow
        if (l >= 2) do_gather(j0 + l - 2, (l + 1) & 1);

        // row l ready when <=2 newest groups pending (rows l+1, l+2)
        asm volatile("cp.async.wait_group 2;" ::: "memory");

        const uint32_t bb = sb + SB + (uint32_t)((l % 3) * SLAB);
        if (l == 0)
            mma_row<false, true >(bb, boff0, boff1, swb0, swb1, bhi, aR, accP, accC);
        else if (l == cnt)
            mma_row<true , false>(bb, boff0, boff1, swb0, swb1, bhi, aR, accP, accC);
        else
            mma_row<true , true >(bb, boff0, boff1, swb0, swb1, bhi, aR, accP, accC);

        // spill accP = GEMM(j0+l-1) into buffer l&1 (permuted layout)
        if (l >= 1) {
            float* Cbm = reinterpret_cast<float*>(smc + SCB + (l & 1) * CBUF) + spOffW;
#pragma unroll
            for (int t = 0; t < 4; ++t) {
                int n = nh * 4 + t;
                int slot = n * 4 + kk;
                Cbm[gr * CBST + slot]            = accP[t][0];
                Cbm[gr * CBST + slot + 33]       = accP[t][1];
                Cbm[(gr + 8) * CBST + slot]      = accP[t][2];
                Cbm[(gr + 8) * CBST + slot + 33] = accP[t][3];
            }
        }
#pragma unroll
        for (int t = 0; t < 4; ++t)
#pragma unroll
            for (int q = 0; q < 4; ++q) { accP[t][q] = accC[t][q]; accC[t][q] = 0.f; }
    }
    __syncthreads();
    do_gather(j0 + cnt - 1, cnt & 1);
}

extern "C" void kernel_launch(void* const* d_in, const int* in_sizes, int n_in,
                              void* d_out, int out_size)
{
    (void)in_sizes; (void)n_in; (void)out_size;
    const float* x1 = (const float*)d_in[0];
    const float* x2 = (const float*)d_in[1];
    float* out = (float*)d_out;

    static bool attr_set = false;
    if (!attr_set) {
        cudaFuncSetAttribute(corr_hmma_kernel, cudaFuncAttributeMaxDynamicSharedMemorySize,
                             SMEM_MAIN);
        attr_set = true;
    }
    cvt_kernel<<<dim3(HH, BATCH, 2), 256>>>(x1, x2);
    corr_hmma_kernel<<<dim3(3, OHH, BATCH), NT, SMEM_MAIN>>>(out);
}